// round 6
// baseline (speedup 1.0000x reference)
#include <cuda_runtime.h>

// Problem constants
// B=64, S=2048, D=64, E=64, H=512, F=4, V=32000
#define TOKENS (64 * 2048)
#define NBLOCKS (TOKENS / 32)

__device__ float g_logdet[4];

// ---------------------------------------------------------------------------
// helpers
// ---------------------------------------------------------------------------
__device__ __forceinline__ unsigned long long dup2(float a) {
    unsigned long long r;
    unsigned int ai = __float_as_uint(a);
    asm("mov.b64 %0, {%1, %1};" : "=l"(r) : "r"(ai));
    return r;
}
__device__ __forceinline__ void fma2(unsigned long long& d, unsigned long long a,
                                     unsigned long long b) {
    asm("fma.rn.f32x2 %0, %1, %2, %0;" : "+l"(d) : "l"(a), "l"(b));
}
__device__ __forceinline__ float2 unpk(unsigned long long v) {
    unsigned int lo, hi;
    asm("mov.b64 {%0, %1}, %2;" : "=r"(lo), "=r"(hi) : "l"(v));
    float2 r;
    r.x = __uint_as_float(lo);
    r.y = __uint_as_float(hi);
    return r;
}
__device__ __forceinline__ float gelu_exact(float x) {
    return 0.5f * x * (1.0f + erff(x * 0.70710678118654752440f));
}
// copy 4096 floats (16KB) global -> smem, 256 threads, float4
__device__ __forceinline__ void copy4k(float* dst, const float* src, int tid) {
    const float4* s = (const float4*)src;
    float4* d = (float4*)dst;
#pragma unroll
    for (int i = 0; i < 4; i++) d[tid + 256 * i] = s[tid + 256 * i];
}

// ---------------------------------------------------------------------------
// slogdet of the 4 conv matrices (64x64 LU w/ partial pivoting)
// ---------------------------------------------------------------------------
__global__ void logdet_kernel(const float* __restrict__ cW) {
    __shared__ float A[64][65];
    __shared__ int piv;
    int f = blockIdx.x;
    int tid = threadIdx.x;  // 64 threads
    for (int j = 0; j < 64; j++) A[j][tid] = cW[f * 4096 + j * 64 + tid];
    __syncthreads();
    for (int j = 0; j < 64; j++) {
        if (tid == 0) {
            int p = j;
            float mv = fabsf(A[j][j]);
            for (int i = j + 1; i < 64; i++) {
                float v = fabsf(A[i][j]);
                if (v > mv) { mv = v; p = i; }
            }
            piv = p;
        }
        __syncthreads();
        int p = piv;
        if (p != j) {
            float t = A[j][tid];
            A[j][tid] = A[p][tid];
            A[p][tid] = t;
        }
        __syncthreads();
        if (tid > j) {
            float fct = A[tid][j] / A[j][j];
            for (int k = j; k < 64; k++) A[tid][k] -= fct * A[j][k];
        }
        __syncthreads();
    }
    if (tid == 0) {
        float s = 0.f;
        for (int j = 0; j < 64; j++) s += logf(fabsf(A[j][j]));
        g_logdet[f] = s;
    }
}

__global__ void init_ldj_kernel(float* __restrict__ ldj) {
    if (threadIdx.x < 64) {
        float s = g_logdet[0] + g_logdet[1] + g_logdet[2] + g_logdet[3];
        ldj[threadIdx.x] = 2048.0f * s;
    }
}

// ---------------------------------------------------------------------------
// fused flow kernel: 32 tokens per block, 256 threads
// warp tm = token group (4 tokens), lane tn = column group (cols 2tn,2tn+1,...)
// smem: ze[32*64] | ext[32*64] | h[32*512] | stage[4096]
// ---------------------------------------------------------------------------
__global__ __launch_bounds__(256, 2) void flow_kernel(
    const float* __restrict__ zin, const int* __restrict__ categ,
    const float* __restrict__ embed, const float* __restrict__ aW,
    const float* __restrict__ ab, const float* __restrict__ cW,
    const float* __restrict__ scf, const float* __restrict__ W0,
    const float* __restrict__ b0, const float* __restrict__ W1,
    const float* __restrict__ b1, const float* __restrict__ W2,
    const float* __restrict__ b2, float* __restrict__ outz,
    float* __restrict__ ldj) {
    extern __shared__ float smem[];
    float* ze = smem;             // 2048 floats
    float* ext = smem + 2048;     // 2048 floats
    float* h = smem + 4096;       // 16384 floats
    float* stage = smem + 20480;  // 4096 floats
    __shared__ int cat[32];
    __shared__ float wsum[8];

    const int tid = threadIdx.x;
    const int tm = tid >> 5;
    const int tn = tid & 31;
    const int t0 = blockIdx.x * 32;
    const int m0 = tm * 4;

    // load z tile (32x64) and categories
    {
        const float4* zg = (const float4*)(zin + (long long)t0 * 64);
        float4* zs = (float4*)ze;
#pragma unroll
        for (int i = 0; i < 2; i++) zs[tid + 256 * i] = zg[tid + 256 * i];
    }
    if (tid < 32) cat[tid] = categ[t0 + tid];
    __syncthreads();
    // gather embeddings (32x64)
    {
        float4* es = (float4*)ext;
#pragma unroll
        for (int i = 0; i < 2; i++) {
            int idx = tid + 256 * i;
            int m = idx >> 4, e4 = idx & 15;
            es[idx] = ((const float4*)embed)[(long long)cat[m] * 16 + e4];
        }
    }
    float ldj_acc = 0.f;

#pragma unroll 1
    for (int f = 0; f < 4; f++) {
        const float* aWf = aW + f * 64 * 128;
        const float* abf = ab + f * 128;
        const float* cWf = cW + f * 64 * 64;
        const float* scff = scf + f * 64;
        const float* W0f = W0 + f * 128 * 512;
        const float* b0f = b0 + f * 512;
        const float* W1f = W1 + f * 512 * 512;
        const float* b1f = b1 + f * 512;
        const float* W2f = W2 + f * 512 * 128;
        const float* b2f = b2 + f * 128;

        // ========== G1: actnorm  nn = ext(32x64) @ aW(64x128) ==========
        {
            unsigned long long acc[4][2] = {{0ull, 0ull}, {0ull, 0ull}, {0ull, 0ull}, {0ull, 0ull}};
#pragma unroll 1
            for (int k0 = 0; k0 < 64; k0 += 32) {
                __syncthreads();
                copy4k(stage, aWf + k0 * 128, tid);
                __syncthreads();
#pragma unroll 4
                for (int kk = 0; kk < 32; kk++) {
                    const float* srow = stage + kk * 128 + 2 * tn;
                    unsigned long long w0 = *(const unsigned long long*)(srow);
                    unsigned long long w1 = *(const unsigned long long*)(srow + 64);
#pragma unroll
                    for (int i = 0; i < 4; i++) {
                        unsigned long long a = dup2(ext[(m0 + i) * 64 + k0 + kk]);
                        fma2(acc[i][0], a, w0);
                        fma2(acc[i][1], a, w1);
                    }
                }
            }
            __syncthreads();
            const int d0 = 2 * tn;
            const float ab0 = abf[d0], ab1 = abf[d0 + 1];
            const float as0 = abf[64 + d0], as1 = abf[65 + d0];
#pragma unroll
            for (int i = 0; i < 4; i++) {
                float2 bi = unpk(acc[i][0]);
                float2 sc = unpk(acc[i][1]);
                float s0 = tanhf(sc.x + as0);
                float s1 = tanhf(sc.y + as1);
                float* zp = ze + (m0 + i) * 64 + d0;
                zp[0] = (zp[0] + bi.x + ab0) * expf(s0);
                zp[1] = (zp[1] + bi.y + ab1) * expf(s1);
                ldj_acc += s0 + s1;
            }
            __syncthreads();
        }

        // ========== G2: conv  z = z(32x64) @ cW(64x64) ==========
        {
            unsigned long long acc[4] = {0ull, 0ull, 0ull, 0ull};
            copy4k(stage, cWf, tid);
            __syncthreads();
#pragma unroll 4
            for (int kk = 0; kk < 64; kk++) {
                unsigned long long w = *(const unsigned long long*)(stage + kk * 64 + 2 * tn);
#pragma unroll
                for (int i = 0; i < 4; i++) {
                    unsigned long long a = dup2(ze[(m0 + i) * 64 + kk]);
                    fma2(acc[i], a, w);
                }
            }
            __syncthreads();
#pragma unroll
            for (int i = 0; i < 4; i++) {
                float2 v = unpk(acc[i]);
                ze[(m0 + i) * 64 + 2 * tn] = v.x;
                ze[(m0 + i) * 64 + 2 * tn + 1] = v.y;
            }
            __syncthreads();
        }

        // ========== G3: h = gelu([z*mask, ext](32x128) @ W0(128x512) + b0) ==
        // mask zeroes z cols 32..63 -> skip W0 rows 32..63 entirely.
        {
            unsigned long long acc[4][8];
#pragma unroll
            for (int i = 0; i < 4; i++)
#pragma unroll
                for (int j = 0; j < 8; j++) acc[i][j] = 0ull;
#pragma unroll 1
            for (int half = 0; half < 2; half++) {
                const float* Abase = half ? ext : ze;
                const int kmax = half ? 64 : 32;
                const int krow0 = half ? 64 : 0;
#pragma unroll 1
                for (int k0 = 0; k0 < kmax; k0 += 8) {
                    __syncthreads();
                    copy4k(stage, W0f + (krow0 + k0) * 512, tid);
                    __syncthreads();
#pragma unroll
                    for (int kk = 0; kk < 8; kk++) {
                        unsigned long long a0 = dup2(Abase[(m0 + 0) * 64 + k0 + kk]);
                        unsigned long long a1 = dup2(Abase[(m0 + 1) * 64 + k0 + kk]);
                        unsigned long long a2 = dup2(Abase[(m0 + 2) * 64 + k0 + kk]);
                        unsigned long long a3 = dup2(Abase[(m0 + 3) * 64 + k0 + kk]);
                        const float* srow = stage + kk * 512 + 2 * tn;
#pragma unroll
                        for (int j = 0; j < 8; j++) {
                            unsigned long long w = *(const unsigned long long*)(srow + 64 * j);
                            fma2(acc[0][j], a0, w);
                            fma2(acc[1][j], a1, w);
                            fma2(acc[2][j], a2, w);
                            fma2(acc[3][j], a3, w);
                        }
                    }
                }
            }
            __syncthreads();
#pragma unroll
            for (int i = 0; i < 4; i++) {
#pragma unroll
                for (int j = 0; j < 8; j++) {
                    int n = 2 * tn + 64 * j;
                    float2 v = unpk(acc[i][j]);
                    h[(m0 + i) * 512 + n] = gelu_exact(v.x + b0f[n]);
                    h[(m0 + i) * 512 + n + 1] = gelu_exact(v.y + b0f[n + 1]);
                }
            }
            __syncthreads();
        }

        // ========== G4: h = gelu(h(32x512) @ W1(512x512) + b1)  (in place) ==
        {
            unsigned long long acc[4][8];
#pragma unroll
            for (int i = 0; i < 4; i++)
#pragma unroll
                for (int j = 0; j < 8; j++) acc[i][j] = 0ull;
#pragma unroll 1
            for (int k0 = 0; k0 < 512; k0 += 8) {
                __syncthreads();
                copy4k(stage, W1f + k0 * 512, tid);
                __syncthreads();
#pragma unroll
                for (int kk = 0; kk < 8; kk++) {
                    unsigned long long a0 = dup2(h[(m0 + 0) * 512 + k0 + kk]);
                    unsigned long long a1 = dup2(h[(m0 + 1) * 512 + k0 + kk]);
                    unsigned long long a2 = dup2(h[(m0 + 2) * 512 + k0 + kk]);
                    unsigned long long a3 = dup2(h[(m0 + 3) * 512 + k0 + kk]);
                    const float* srow = stage + kk * 512 + 2 * tn;
#pragma unroll
                    for (int j = 0; j < 8; j++) {
                        unsigned long long w = *(const unsigned long long*)(srow + 64 * j);
                        fma2(acc[0][j], a0, w);
                        fma2(acc[1][j], a1, w);
                        fma2(acc[2][j], a2, w);
                        fma2(acc[3][j], a3, w);
                    }
                }
            }
            __syncthreads();  // all reads of h done before overwrite
#pragma unroll
            for (int i = 0; i < 4; i++) {
#pragma unroll
                for (int j = 0; j < 8; j++) {
                    int n = 2 * tn + 64 * j;
                    float2 v = unpk(acc[i][j]);
                    h[(m0 + i) * 512 + n] = gelu_exact(v.x + b1f[n]);
                    h[(m0 + i) * 512 + n + 1] = gelu_exact(v.y + b1f[n + 1]);
                }
            }
            __syncthreads();
        }

        // ========== G5: coupling. Only output cols 64..127 of W2 matter ====
        // (s,t for d<32 are masked to zero -> z unchanged there)
        {
            unsigned long long acc[4] = {0ull, 0ull, 0ull, 0ull};
#pragma unroll 1
            for (int k0 = 0; k0 < 512; k0 += 32) {
                __syncthreads();
                copy4k(stage, W2f + k0 * 128, tid);
                __syncthreads();
#pragma unroll 4
                for (int kk = 0; kk < 32; kk++) {
                    unsigned long long w =
                        *(const unsigned long long*)(stage + kk * 128 + 64 + 2 * tn);
#pragma unroll
                    for (int i = 0; i < 4; i++) {
                        unsigned long long a = dup2(h[(m0 + i) * 512 + k0 + kk]);
                        fma2(acc[i], a, w);
                    }
                }
            }
            __syncthreads();
            const int d = 32 + tn;  // s = col 2d = 64+2tn, t = col 2d+1
            const float sf = expf(scff[d]);
            const float den = fmaxf(sf, 1.0f);
            const float bs = b2f[64 + 2 * tn];
            const float bt = b2f[65 + 2 * tn];
#pragma unroll
            for (int i = 0; i < 4; i++) {
                float2 v = unpk(acc[i]);
                float s = tanhf((v.x + bs) / den) * sf;
                float tt = v.y + bt;
                float* zp = ze + (m0 + i) * 64 + d;
                zp[0] = (zp[0] + tt) * expf(s);
                ldj_acc += s;
            }
            __syncthreads();
        }
    }  // flows

    // write z tile out
    {
        float4* og = (float4*)(outz + (long long)t0 * 64);
        const float4* zs = (const float4*)ze;
#pragma unroll
        for (int i = 0; i < 2; i++) og[tid + 256 * i] = zs[tid + 256 * i];
    }
    // ldj: block reduce + atomic into per-batch slot
#pragma unroll
    for (int o = 16; o; o >>= 1) ldj_acc += __shfl_xor_sync(0xffffffffu, ldj_acc, o);
    if (tn == 0) wsum[tm] = ldj_acc;
    __syncthreads();
    if (tid == 0) {
        float s = 0.f;
#pragma unroll
        for (int i = 0; i < 8; i++) s += wsum[i];
        atomicAdd(&ldj[blockIdx.x >> 6], s);  // 64 blocks per batch
    }
}

// ---------------------------------------------------------------------------
extern "C" void kernel_launch(void* const* d_in, const int* in_sizes, int n_in,
                              void* d_out, int out_size) {
    const float* z = (const float*)d_in[0];
    const int* categ = (const int*)d_in[1];
    const float* embed = (const float*)d_in[2];
    const float* actnorm_W = (const float*)d_in[3];
    const float* actnorm_b = (const float*)d_in[4];
    const float* conv_W = (const float*)d_in[5];
    const float* scaling_factor = (const float*)d_in[6];
    const float* W0 = (const float*)d_in[7];
    const float* b0 = (const float*)d_in[8];
    const float* W1 = (const float*)d_in[9];
    const float* b1 = (const float*)d_in[10];
    const float* W2 = (const float*)d_in[11];
    const float* b2 = (const float*)d_in[12];

    float* outz = (float*)d_out;
    float* ldj = outz + (long long)TOKENS * 64;

    static const int SMEM_BYTES = 24576 * sizeof(float);  // 98304
    cudaFuncSetAttribute(flow_kernel, cudaFuncAttributeMaxDynamicSharedMemorySize,
                         SMEM_BYTES);

    logdet_kernel<<<4, 64>>>(conv_W);
    init_ldj_kernel<<<1, 64>>>(ldj);
    flow_kernel<<<NBLOCKS, 256, SMEM_BYTES>>>(z, categ, embed, actnorm_W, actnorm_b,
                                              conv_W, scaling_factor, W0, b0, W1, b1,
                                              W2, b2, outz, ldj);
}

// round 7
// speedup vs baseline: 1.7432x; 1.7432x over previous
#include <cuda_runtime.h>
#include <cstdint>

// B=64,S=2048,D=64,E=64,H=512,F=4,V=32000
#define TOKENS (64 * 2048)
#define NBLK (TOKENS / 64)
typedef unsigned long long ULL;
typedef unsigned int U32;

__device__ float g_logdet[4];
__device__ float g_W0p[4 * 12 * 64 * 64];  // [f][kt][nt][64] frag-packed tf32 (K'=96)
__device__ float g_W1p[4 * 64 * 64 * 64];
__device__ float g_W2p[4 * 64 * 8 * 64];  // cols 64..127 only

// smem float offsets
#define ZE 0       // 64x68 fp32 z
#define EXT 4352   // 64x64 fp32 ext
#define G3A 8448   // 4x12x128 A-frag tf32 (masked z + ext)
#define SB 14592   // biases: b0[512] b1[512] b2[128] ab[128]
#define RING 15872 // 8192 floats staging ring
#define HA 24064   // 4x64x128 A-frag tf32 h
#define SMEMF 56832
#define SMEMB (SMEMF * 4)

// ---------------- helpers ----------------
__device__ __forceinline__ ULL dup2(float a) {
    ULL r; U32 ai = __float_as_uint(a);
    asm("mov.b64 %0, {%1, %1};" : "=l"(r) : "r"(ai));
    return r;
}
__device__ __forceinline__ void fma2(ULL& d, ULL a, ULL b) {
    asm("fma.rn.f32x2 %0, %1, %2, %0;" : "+l"(d) : "l"(a), "l"(b));
}
__device__ __forceinline__ float2 unpk(ULL v) {
    U32 lo, hi;
    asm("mov.b64 {%0, %1}, %2;" : "=r"(lo), "=r"(hi) : "l"(v));
    float2 r; r.x = __uint_as_float(lo); r.y = __uint_as_float(hi);
    return r;
}
__device__ __forceinline__ float gelu(float x) {
    return 0.5f * x * (1.0f + erff(x * 0.70710678118654752440f));
}
__device__ __forceinline__ float to_tf32(float x) {
    float r;
    asm("cvt.rna.tf32.f32 %0, %1;" : "=f"(r) : "f"(x));
    return r;
}
__device__ __forceinline__ U32 smem_u32(const void* p) {
    U32 a;
    asm("{ .reg .u64 t; cvta.to.shared.u64 t, %1; cvt.u32.u64 %0, t; }" : "=r"(a) : "l"(p));
    return a;
}
#define CPA16(d, s) asm volatile("cp.async.cg.shared.global [%0], [%1], 16;" ::"r"(d), "l"(s))
#define CPC() asm volatile("cp.async.commit_group;" ::: "memory")
#define CPW0() asm volatile("cp.async.wait_group 0;" ::: "memory")
#define CPW1() asm volatile("cp.async.wait_group 1;" ::: "memory")

__device__ __forceinline__ void mma8(float* c, uint4 a, uint2 b) {
    asm volatile(
        "mma.sync.aligned.m16n8k8.row.col.f32.tf32.tf32.f32 "
        "{%0,%1,%2,%3},{%4,%5,%6,%7},{%8,%9},{%0,%1,%2,%3};"
        : "+f"(c[0]), "+f"(c[1]), "+f"(c[2]), "+f"(c[3])
        : "r"(a.x), "r"(a.y), "r"(a.z), "r"(a.w), "r"(b.x), "r"(b.y));
}
__device__ __forceinline__ void stage_cp(U32 dstU, const float* src, int n4, int tid) {
    for (int i = tid; i < n4; i += 256) CPA16(dstU + i * 16, src + i * 4);
}

// ---------------- weight pack: B-fragment order, tf32 ----------------
__global__ void packB(const float* __restrict__ src, float* __restrict__ dst, int K,
                      int N, int KT, int NT, int nOff, int kMode) {
    int f = blockIdx.y, kt = blockIdx.x, tid = threadIdx.x;
    const float* s = src + (long long)f * K * N;
    float* d = dst + (long long)(f * KT + kt) * NT * 64;
    for (int i = tid; i < NT * 64; i += 256) {
        int nt = i >> 6, j = i & 63, lane = j >> 1, rr = j & 1;
        int kk = kt * 8 + (lane & 3) + 4 * rr;
        int n = nt * 8 + (lane >> 2) + nOff;
        if (kMode && kk >= 32) kk += 32;  // W0: skip masked-z rows 32..63
        d[i] = to_tf32(s[kk * N + n]);
    }
}

// ---------------- slogdet (64x64 LU) ----------------
__global__ void logdet_kernel(const float* __restrict__ cW) {
    __shared__ float A[64][65];
    __shared__ int piv;
    int f = blockIdx.x, tid = threadIdx.x;
    for (int j = 0; j < 64; j++) A[j][tid] = cW[f * 4096 + j * 64 + tid];
    __syncthreads();
    for (int j = 0; j < 64; j++) {
        if (tid == 0) {
            int p = j; float mv = fabsf(A[j][j]);
            for (int i = j + 1; i < 64; i++) {
                float v = fabsf(A[i][j]);
                if (v > mv) { mv = v; p = i; }
            }
            piv = p;
        }
        __syncthreads();
        int p = piv;
        if (p != j) { float t = A[j][tid]; A[j][tid] = A[p][tid]; A[p][tid] = t; }
        __syncthreads();
        if (tid > j) {
            float fct = A[tid][j] / A[j][j];
            for (int k = j; k < 64; k++) A[tid][k] -= fct * A[j][k];
        }
        __syncthreads();
    }
    if (tid == 0) {
        float s = 0.f;
        for (int j = 0; j < 64; j++) s += logf(fabsf(A[j][j]));
        g_logdet[f] = s;
    }
}
__global__ void init_ldj_kernel(float* __restrict__ ldj) {
    if (threadIdx.x < 64) {
        float s = g_logdet[0] + g_logdet[1] + g_logdet[2] + g_logdet[3];
        ldj[threadIdx.x] = 2048.0f * s;
    }
}

// ---------------- N=512 mma GEMM (warps: 4 mtiles x 2 nhalves) ----------------
template <int KTG>
__device__ __forceinline__ void gemm512(float (*acc)[4], const float* Bf,
                                        const float* aReg, U32 ringU,
                                        const float* ringF, int tid, int lane, int mt,
                                        int nh) {
    stage_cp(ringU, Bf, 1024, tid); CPC();
    stage_cp(ringU + 16384, Bf + 4096, 1024, tid); CPC();
    for (int kt = 0; kt < KTG; kt++) {
        if (kt + 1 < KTG) CPW1(); else CPW0();
        __syncthreads();
        uint4 av = *(const uint4*)(aReg + (mt * KTG + kt) * 128 + lane * 4);
        const float* bp = ringF + (kt & 1) * 4096 + nh * 2048 + lane * 2;
#pragma unroll
        for (int nt = 0; nt < 32; nt++) {
            uint2 bv = *(const uint2*)(bp + nt * 64);
            mma8(acc[nt], av, bv);
        }
        __syncthreads();
        if (kt + 2 < KTG) {
            stage_cp(ringU + (kt & 1) * 16384, Bf + (kt + 2) * 4096, 1024, tid);
            CPC();
        }
    }
}
// epilogue: gelu(acc+bias) -> hA (A-frag, tf32)
__device__ __forceinline__ void epiH(float (*acc)[4], const float* bias, float* hA,
                                     int lane, int mt, int nh) {
    int r = lane >> 2, c2 = 2 * (lane & 3);
#pragma unroll
    for (int nt = 0; nt < 32; nt++) {
        int ntg = nh * 32 + nt;
#pragma unroll
        for (int q = 0; q < 4; q++) {
            int m = mt * 16 + r + ((q >> 1) << 3);
            int n = ntg * 8 + c2 + (q & 1);
            float v = to_tf32(gelu(acc[nt][q] + bias[n]));
            int ld = (m & 7) * 4 + (n & 3);
            int rg = ((m >> 3) & 1) + 2 * ((n >> 2) & 1);
            hA[(mt * 64 + ntg) * 128 + ld * 4 + rg] = v;
        }
    }
}

// ---------------- fused flow kernel: 64 tokens/CTA, 256 threads ----------------
__global__ __launch_bounds__(256, 1) void flow_kernel(
    const float* __restrict__ zin, const int* __restrict__ categ,
    const float* __restrict__ embed, const float* __restrict__ aW,
    const float* __restrict__ ab, const float* __restrict__ cW,
    const float* __restrict__ scf, const float* __restrict__ b0g,
    const float* __restrict__ b1g, const float* __restrict__ b2g,
    float* __restrict__ outz, float* __restrict__ ldj) {
    extern __shared__ float sm[];
    __shared__ int cat[64];
    __shared__ float wsum[8];
    const int tid = threadIdx.x, wid = tid >> 5, lane = tid & 31;
    const int mt = wid & 3, nh = wid >> 2;  // mma roles
    const int m0 = wid * 8, tn = lane;      // scalar roles (8 tokens/warp)
    const int t0 = blockIdx.x * 64;
    float* zef = sm + ZE;
    float* extf = sm + EXT;
    float* g3a = sm + G3A;
    float* sb = sm + SB;
    float* ringF = sm + RING;
    float* hA = sm + HA;
    const U32 ringU = smem_u32(sm) + RING * 4;

    // init loads
    for (int i = tid; i < 4096; i += 256) zef[(i >> 6) * 68 + (i & 63)] = zin[(long long)t0 * 64 + i];
    if (tid < 64) cat[tid] = categ[t0 + tid];
    __syncthreads();
    for (int i = tid; i < 1024; i += 256) {
        int m = i >> 4, e4 = i & 15;
        *(float4*)(extf + i * 4) = ((const float4*)embed)[(long long)cat[m] * 16 + e4];
    }
    __syncthreads();
    // pack ext -> G3A ktiles 4..11 (tf32 A-frag)
    for (int i = tid; i < 4096; i += 256) {
        int m = i >> 6, e = i & 63, kp = 32 + e;
        int ld = (m & 7) * 4 + (kp & 3), rg = ((m >> 3) & 1) + 2 * ((kp >> 2) & 1);
        g3a[((m >> 4) * 12 + (kp >> 3)) * 128 + ld * 4 + rg] = to_tf32(extf[i]);
    }
    float ldj_acc = 0.f;

#pragma unroll 1
    for (int f = 0; f < 4; f++) {
        // biases -> smem
        __syncthreads();
        for (int i = tid; i < 512; i += 256) sb[i] = b0g[f * 512 + i];
        for (int i = tid; i < 512; i += 256) sb[512 + i] = b1g[f * 512 + i];
        if (tid < 128) sb[1024 + tid] = b2g[f * 128 + tid];
        if (tid < 128) sb[1152 + tid] = ab[f * 128 + tid];
        // stage aW (8192 floats) for G1
        stage_cp(ringU, aW + f * 8192, 2048, tid); CPC(); CPW0();
        __syncthreads();

        // G1: actnorm (scalar fp32x2)
        {
            ULL acc[8][2];
#pragma unroll
            for (int i = 0; i < 8; i++) acc[i][0] = acc[i][1] = 0ull;
#pragma unroll 4
            for (int kk = 0; kk < 64; kk++) {
                ULL w0 = *(const ULL*)(ringF + kk * 128 + 2 * tn);
                ULL w1 = *(const ULL*)(ringF + kk * 128 + 64 + 2 * tn);
#pragma unroll
                for (int i = 0; i < 8; i++) {
                    ULL a = dup2(extf[(m0 + i) * 64 + kk]);
                    fma2(acc[i][0], a, w0);
                    fma2(acc[i][1], a, w1);
                }
            }
            int d0 = 2 * tn;
            float ab0 = sb[1152 + d0], ab1 = sb[1153 + d0];
            float as0 = sb[1216 + d0], as1 = sb[1217 + d0];
#pragma unroll
            for (int i = 0; i < 8; i++) {
                float2 bi = unpk(acc[i][0]);
                float2 sc = unpk(acc[i][1]);
                float s0 = tanhf(sc.x + as0), s1 = tanhf(sc.y + as1);
                float* zp = zef + (m0 + i) * 68 + d0;
                zp[0] = (zp[0] + bi.x + ab0) * expf(s0);
                zp[1] = (zp[1] + bi.y + ab1) * expf(s1);
                ldj_acc += s0 + s1;
            }
            __syncthreads();
        }
        // G2: 1x1 conv (scalar fp32x2)
        {
            stage_cp(ringU, cW + f * 4096, 1024, tid); CPC(); CPW0();
            __syncthreads();
            ULL acc[8];
#pragma unroll
            for (int i = 0; i < 8; i++) acc[i] = 0ull;
#pragma unroll 4
            for (int kk = 0; kk < 64; kk++) {
                ULL w = *(const ULL*)(ringF + kk * 64 + 2 * tn);
#pragma unroll
                for (int i = 0; i < 8; i++) fma2(acc[i], dup2(zef[(m0 + i) * 68 + kk]), w);
            }
            __syncthreads();
#pragma unroll
            for (int i = 0; i < 8; i++) {
                float2 v = unpk(acc[i]);
                zef[(m0 + i) * 68 + 2 * tn] = v.x;
                zef[(m0 + i) * 68 + 2 * tn + 1] = v.y;
            }
            __syncthreads();
        }
        // pack masked z -> G3A ktiles 0..3
        for (int i = tid; i < 2048; i += 256) {
            int m = i >> 5, zc = i & 31;
            int ld = (m & 7) * 4 + (zc & 3), rg = ((m >> 3) & 1) + 2 * ((zc >> 2) & 1);
            g3a[((m >> 4) * 12 + (zc >> 3)) * 128 + ld * 4 + rg] = to_tf32(zef[m * 68 + zc]);
        }
        __syncthreads();

        // G3: h = gelu([z*mask,ext] @ W0) via mma, K=96
        {
            float acc[32][4];
#pragma unroll
            for (int i = 0; i < 32; i++)
#pragma unroll
                for (int q = 0; q < 4; q++) acc[i][q] = 0.f;
            gemm512<12>(acc, g_W0p + f * 12 * 4096, g3a, ringU, ringF, tid, lane, mt, nh);
            __syncthreads();
            epiH(acc, sb, hA, lane, mt, nh);
            __syncthreads();
        }
        // G4: h = gelu(h @ W1), K=512, in-place via regs
        {
            float acc[32][4];
#pragma unroll
            for (int i = 0; i < 32; i++)
#pragma unroll
                for (int q = 0; q < 4; q++) acc[i][q] = 0.f;
            gemm512<64>(acc, g_W1p + f * 64 * 4096, hA, ringU, ringF, tid, lane, mt, nh);
            __syncthreads();
            epiH(acc, sb + 512, hA, lane, mt, nh);
            __syncthreads();
        }
        // G5: coupling, N=64 (cols 64..127 of W2)
        {
            float acc[4][4];
#pragma unroll
            for (int i = 0; i < 4; i++)
#pragma unroll
                for (int q = 0; q < 4; q++) acc[i][q] = 0.f;
            const float* Bf = g_W2p + f * 64 * 512;
            stage_cp(ringU, Bf, 128, tid); CPC();
            stage_cp(ringU + 2048, Bf + 512, 128, tid); CPC();
            for (int kt = 0; kt < 64; kt++) {
                if (kt + 1 < 64) CPW1(); else CPW0();
                __syncthreads();
                uint4 av = *(const uint4*)(hA + (mt * 64 + kt) * 128 + lane * 4);
                const float* bp = ringF + (kt & 1) * 512 + nh * 256 + lane * 2;
#pragma unroll
                for (int nt = 0; nt < 4; nt++) {
                    uint2 bv = *(const uint2*)(bp + nt * 64);
                    mma8(acc[nt], av, bv);
                }
                __syncthreads();
                if (kt + 2 < 64) {
                    stage_cp(ringU + (kt & 1) * 2048, Bf + (kt + 2) * 512, 128, tid);
                    CPC();
                }
            }
            __syncthreads();
            int r = lane >> 2, cc = lane & 3;
#pragma unroll
            for (int nt = 0; nt < 4; nt++) {
                int ntg = nh * 4 + nt;
                int d = 32 + ntg * 4 + cc;
                float sf = expf(scf[f * 64 + d]);
                float den = fmaxf(sf, 1.0f);
                float bs = sb[1024 + 64 + ntg * 8 + 2 * cc];
                float bt = sb[1024 + 65 + ntg * 8 + 2 * cc];
#pragma unroll
                for (int q = 0; q < 2; q++) {
                    int m = mt * 16 + r + q * 8;
                    float sr = acc[nt][2 * q] + bs, tr = acc[nt][2 * q + 1] + bt;
                    float s = tanhf(sr / den) * sf;
                    zef[m * 68 + d] = (zef[m * 68 + d] + tr) * expf(s);
                    ldj_acc += s;
                }
            }
            __syncthreads();
        }
    }  // flows

    // output
    for (int i = tid; i < 4096; i += 256)
        outz[(long long)t0 * 64 + i] = zef[(i >> 6) * 68 + (i & 63)];
#pragma unroll
    for (int o = 16; o; o >>= 1) ldj_acc += __shfl_xor_sync(0xffffffffu, ldj_acc, o);
    if (lane == 0) wsum[wid] = ldj_acc;
    __syncthreads();
    if (tid == 0) {
        float s = 0.f;
#pragma unroll
        for (int i = 0; i < 8; i++) s += wsum[i];
        atomicAdd(&ldj[blockIdx.x >> 5], s);  // 32 blocks per batch
    }
}

// ---------------------------------------------------------------------------
extern "C" void kernel_launch(void* const* d_in, const int* in_sizes, int n_in,
                              void* d_out, int out_size) {
    const float* z = (const float*)d_in[0];
    const int* categ = (const int*)d_in[1];
    const float* embed = (const float*)d_in[2];
    const float* actnorm_W = (const float*)d_in[3];
    const float* actnorm_b = (const float*)d_in[4];
    const float* conv_W = (const float*)d_in[5];
    const float* scaling_factor = (const float*)d_in[6];
    const float* W0 = (const float*)d_in[7];
    const float* b0 = (const float*)d_in[8];
    const float* W1 = (const float*)d_in[9];
    const float* b1 = (const float*)d_in[10];
    const float* W2 = (const float*)d_in[11];
    const float* b2 = (const float*)d_in[12];

    float* outz = (float*)d_out;
    float* ldj = outz + (long long)TOKENS * 64;
    float *w0p, *w1p, *w2p;
    cudaGetSymbolAddress((void**)&w0p, g_W0p);
    cudaGetSymbolAddress((void**)&w1p, g_W1p);
    cudaGetSymbolAddress((void**)&w2p, g_W2p);

    cudaFuncSetAttribute(flow_kernel, cudaFuncAttributeMaxDynamicSharedMemorySize,
                         SMEMB);

    packB<<<dim3(12, 4), 256>>>(W0, w0p, 128, 512, 12, 64, 0, 1);
    packB<<<dim3(64, 4), 256>>>(W1, w1p, 512, 512, 64, 64, 0, 0);
    packB<<<dim3(64, 4), 256>>>(W2, w2p, 512, 128, 64, 8, 64, 0);
    logdet_kernel<<<4, 64>>>(conv_W);
    init_ldj_kernel<<<1, 64>>>(ldj);
    flow_kernel<<<NBLK, 256, SMEMB>>>(z, categ, embed, actnorm_W, actnorm_b, conv_W,
                                      scaling_factor, b0, b1, b2, outz, ldj);
}

// round 8
// speedup vs baseline: 2.6269x; 1.5069x over previous
#include <cuda_runtime.h>
#include <cstdint>

// B=64,S=2048,D=64,E=64,H=512,F=4,V=32000
#define TOKENS (64 * 2048)
#define NBLK (TOKENS / 64)
typedef unsigned long long ULL;
typedef unsigned int U32;

__device__ float g_logdet[4];
__device__ U32 g_W0p[4 * 6 * 64 * 64];    // [f][kt][nt*64+lane*2+rr] bf16x2, K'=96
__device__ U32 g_W1p[4 * 32 * 64 * 64];   // K=512
__device__ U32 g_W2p[4 * 32 * 8 * 64];    // W2 cols 64..127, K=512

// smem float offsets
#define ZE 0        // 64x68 fp32 z
#define EXT 4352    // 64x64 fp32 ext
#define G3A 8448    // 3072 u32: A-frags bf16 [mtB][kt<6][128]
#define SB 11520    // b0[512] b1[512] b2[128] ab[128]
#define RING 12800  // 3 x 4096 u32 (16KB) staging ring
#define HA 25088    // 16384 u32: h A-frags bf16 [mt][kt<32][128]
#define SMEMF 41472
#define SMEMB (SMEMF * 4)

// ---------------- helpers ----------------
__device__ __forceinline__ ULL dup2(float a) {
    ULL r; U32 ai = __float_as_uint(a);
    asm("mov.b64 %0, {%1, %1};" : "=l"(r) : "r"(ai));
    return r;
}
__device__ __forceinline__ void fma2(ULL& d, ULL a, ULL b) {
    asm("fma.rn.f32x2 %0, %1, %2, %0;" : "+l"(d) : "l"(a), "l"(b));
}
__device__ __forceinline__ float2 unpk(ULL v) {
    U32 lo, hi;
    asm("mov.b64 {%0, %1}, %2;" : "=r"(lo), "=r"(hi) : "l"(v));
    float2 r; r.x = __uint_as_float(lo); r.y = __uint_as_float(hi);
    return r;
}
__device__ __forceinline__ float gelu(float x) {
    return 0.5f * x * (1.0f + erff(x * 0.70710678118654752440f));
}
__device__ __forceinline__ U32 pack_bf16(float lo, float hi) {
    U32 r;
    asm("cvt.rn.bf16x2.f32 %0, %1, %2;" : "=r"(r) : "f"(hi), "f"(lo));
    return r;
}
__device__ __forceinline__ U32 smem_u32(const void* p) {
    U32 a;
    asm("{ .reg .u64 t; cvta.to.shared.u64 t, %1; cvt.u32.u64 %0, t; }" : "=r"(a) : "l"(p));
    return a;
}
#define CPA16(d, s) asm volatile("cp.async.cg.shared.global [%0], [%1], 16;" ::"r"(d), "l"(s))
#define CPC() asm volatile("cp.async.commit_group;" ::: "memory")
#define CPW0() asm volatile("cp.async.wait_group 0;" ::: "memory")
#define CPW1() asm volatile("cp.async.wait_group 1;" ::: "memory")

__device__ __forceinline__ void mma16(float* c, uint4 a, uint2 b) {
    asm volatile(
        "mma.sync.aligned.m16n8k16.row.col.f32.bf16.bf16.f32 "
        "{%0,%1,%2,%3},{%4,%5,%6,%7},{%8,%9},{%0,%1,%2,%3};"
        : "+f"(c[0]), "+f"(c[1]), "+f"(c[2]), "+f"(c[3])
        : "r"(a.x), "r"(a.y), "r"(a.z), "r"(a.w), "r"(b.x), "r"(b.y));
}
__device__ __forceinline__ void stage_cp(U32 dstU, const float* src, int n4, int tid) {
    for (int i = tid; i < n4; i += 256) CPA16(dstU + i * 16, src + i * 4);
}

// ---------------- weight pack: bf16 B-fragment order ----------------
__global__ void packB(const float* __restrict__ src, U32* __restrict__ dst, int N,
                      int KT, int NT, int nOff, int kMode) {
    int f = blockIdx.y, kt = blockIdx.x, tid = threadIdx.x;
    const float* s = src + (long long)f * (kMode ? 128 : 512) * N;
    U32* d = dst + (long long)(f * KT + kt) * NT * 64;
    for (int i = tid; i < NT * 64; i += 256) {
        int nt = i >> 6, j = i & 63, lane = j >> 1, rr = j & 1;
        int k0 = kt * 16 + 2 * (lane & 3) + 8 * rr;
        int n = nt * 8 + (lane >> 2) + nOff;
        if (kMode && k0 >= 32) k0 += 32;  // W0: skip masked-z rows 32..63
        d[i] = pack_bf16(s[k0 * N + n], s[(k0 + 1) * N + n]);
    }
}

// ---------------- slogdet (64x64 LU) ----------------
__global__ void logdet_kernel(const float* __restrict__ cW) {
    __shared__ float A[64][65];
    __shared__ int piv;
    int f = blockIdx.x, tid = threadIdx.x;
    for (int j = 0; j < 64; j++) A[j][tid] = cW[f * 4096 + j * 64 + tid];
    __syncthreads();
    for (int j = 0; j < 64; j++) {
        if (tid == 0) {
            int p = j; float mv = fabsf(A[j][j]);
            for (int i = j + 1; i < 64; i++) {
                float v = fabsf(A[i][j]);
                if (v > mv) { mv = v; p = i; }
            }
            piv = p;
        }
        __syncthreads();
        int p = piv;
        if (p != j) { float t = A[j][tid]; A[j][tid] = A[p][tid]; A[p][tid] = t; }
        __syncthreads();
        if (tid > j) {
            float fct = A[tid][j] / A[j][j];
            for (int k = j; k < 64; k++) A[tid][k] -= fct * A[j][k];
        }
        __syncthreads();
    }
    if (tid == 0) {
        float s = 0.f;
        for (int j = 0; j < 64; j++) s += logf(fabsf(A[j][j]));
        g_logdet[f] = s;
    }
}
__global__ void init_ldj_kernel(float* __restrict__ ldj) {
    if (threadIdx.x < 64) {
        float s = g_logdet[0] + g_logdet[1] + g_logdet[2] + g_logdet[3];
        ldj[threadIdx.x] = 2048.0f * s;
    }
}

// ---------------- gemm: warp = n-slice (NTW ntiles), all 4 m-tiles ----------
// 3-buffer ring, ONE syncthreads per kt; stage kt+2 overlaps mma on kt.
template <int KT, int NTW, int TSZ, int KTA>
__device__ __forceinline__ void gemmW(float (*acc)[4], const U32* __restrict__ Bg,
                                      const U32* __restrict__ AU, U32 ringU,
                                      const U32* __restrict__ ringFU, int tid,
                                      int lane, int wid) {
    __syncthreads();  // ring safe to overwrite
    // prologue: stage tiles 0,1
    for (int t = 0; t < 2 && t < KT; t++) {
        const float* src = (const float*)(Bg + t * TSZ);
        stage_cp(ringU + t * 16384, src, TSZ / 4, tid);
        CPC();
    }
    for (int kt = 0; kt < KT; kt++) {
        if (kt + 1 < KT) { CPW1(); } else { CPW0(); }
        __syncthreads();
        if (kt + 2 < KT) {
            const float* src = (const float*)(Bg + (kt + 2) * TSZ);
            stage_cp(ringU + ((kt + 2) % 3) * 16384, src, TSZ / 4, tid);
            CPC();
        }
        const U32* bp = ringFU + (kt % 3) * 4096 + wid * (NTW * 64) + lane * 2;
#pragma unroll
        for (int mtl = 0; mtl < 4; mtl++) {
            uint4 av = *(const uint4*)(AU + (mtl * KTA + kt) * 128 + lane * 4);
#pragma unroll
            for (int nt = 0; nt < NTW; nt++) {
                uint2 bv = *(const uint2*)(bp + nt * 64);
                mma16(acc[mtl * NTW + nt], av, bv);
            }
        }
    }
}

// epilogue: gelu(acc+bias) -> hA bf16 A-frags
__device__ __forceinline__ void epiH512(float (*acc)[4], const float* __restrict__ bias,
                                        U32* __restrict__ hAU, int lane, int wid) {
    int c2 = 2 * (lane & 3);
#pragma unroll
    for (int mtl = 0; mtl < 4; mtl++)
#pragma unroll
        for (int nt = 0; nt < 8; nt++) {
            int ntg = wid * 8 + nt;
            float* a = acc[mtl * 8 + nt];
            int n0 = ntg * 8 + c2;
            float b0v = bias[n0], b1v = bias[n0 + 1];
            U32 base = (U32)(mtl * 32 + (ntg >> 1)) * 128 + lane * 4 + 2 * (ntg & 1);
            hAU[base + 0] = pack_bf16(gelu(a[0] + b0v), gelu(a[1] + b1v));
            hAU[base + 1] = pack_bf16(gelu(a[2] + b0v), gelu(a[3] + b1v));
        }
}

// ---------------- fused flow kernel: 64 tokens/CTA, 256 threads ----------------
__global__ __launch_bounds__(256, 1) void flow_kernel(
    const float* __restrict__ zin, const int* __restrict__ categ,
    const float* __restrict__ embed, const float* __restrict__ aW,
    const float* __restrict__ ab, const float* __restrict__ cW,
    const float* __restrict__ scf, const float* __restrict__ b0g,
    const float* __restrict__ b1g, const float* __restrict__ b2g,
    float* __restrict__ outz, float* __restrict__ ldj) {
    extern __shared__ float sm[];
    __shared__ int cat[64];
    __shared__ float wsum[8];
    const int tid = threadIdx.x, wid = tid >> 5, lane = tid & 31;
    const int m0 = wid * 8, tn = lane;
    const int t0 = blockIdx.x * 64;
    float* zef = sm + ZE;
    float* extf = sm + EXT;
    float* sb = sm + SB;
    float* ringF = sm + RING;
    U32* g3aU = (U32*)(sm + G3A);
    U32* hAU = (U32*)(sm + HA);
    const U32* ringFU = (const U32*)(sm + RING);
    const U32 ringU = smem_u32(sm) + RING * 4;

    // init loads
    for (int i = tid; i < 4096; i += 256)
        zef[(i >> 6) * 68 + (i & 63)] = zin[(long long)t0 * 64 + i];
    if (tid < 64) cat[tid] = categ[t0 + tid];
    __syncthreads();
    for (int i = tid; i < 1024; i += 256) {
        int m = i >> 4, e4 = i & 15;
        *(float4*)(extf + i * 4) = ((const float4*)embed)[(long long)cat[m] * 16 + e4];
    }
    __syncthreads();
    // pack ext -> G3A ktiles 2..5 (bf16 A-frags), once
    for (int i = tid; i < 2048; i += 256) {
        int m = i >> 5, p = i & 31;
        int kt = 2 + (p >> 3);
        int ln = (m & 7) * 4 + (p & 3);
        int rr = ((m >> 3) & 1) + 2 * ((p >> 2) & 1);
        g3aU[((m >> 4) * 6 + kt) * 128 + ln * 4 + rr] =
            pack_bf16(extf[m * 64 + 2 * p], extf[m * 64 + 2 * p + 1]);
    }
    float ldj_acc = 0.f;

#pragma unroll 1
    for (int f = 0; f < 4; f++) {
        __syncthreads();
        for (int i = tid; i < 512; i += 256) sb[i] = b0g[f * 512 + i];
        for (int i = tid; i < 512; i += 256) sb[512 + i] = b1g[f * 512 + i];
        if (tid < 128) sb[1024 + tid] = b2g[f * 128 + tid];
        if (tid < 128) sb[1152 + tid] = ab[f * 128 + tid];
        stage_cp(ringU, aW + f * 8192, 2048, tid);
        CPC(); CPW0();
        __syncthreads();

        // G1: actnorm (scalar fp32x2, ext fp32)
        {
            ULL acc[8][2];
#pragma unroll
            for (int i = 0; i < 8; i++) acc[i][0] = acc[i][1] = 0ull;
#pragma unroll 4
            for (int kk = 0; kk < 64; kk++) {
                ULL w0 = *(const ULL*)(ringF + kk * 128 + 2 * tn);
                ULL w1 = *(const ULL*)(ringF + kk * 128 + 64 + 2 * tn);
#pragma unroll
                for (int i = 0; i < 8; i++) {
                    ULL a = dup2(extf[(m0 + i) * 64 + kk]);
                    fma2(acc[i][0], a, w0);
                    fma2(acc[i][1], a, w1);
                }
            }
            int d0 = 2 * tn;
            float ab0 = sb[1152 + d0], ab1 = sb[1153 + d0];
            float as0 = sb[1216 + d0], as1 = sb[1217 + d0];
#pragma unroll
            for (int i = 0; i < 8; i++) {
                float2 bi = unpk(acc[i][0]);
                float2 sc = unpk(acc[i][1]);
                float s0 = tanhf(sc.x + as0), s1 = tanhf(sc.y + as1);
                float* zp = zef + (m0 + i) * 68 + d0;
                zp[0] = (zp[0] + bi.x + ab0) * expf(s0);
                zp[1] = (zp[1] + bi.y + ab1) * expf(s1);
                ldj_acc += s0 + s1;
            }
            __syncthreads();
        }
        // G2: 1x1 conv (scalar fp32x2)
        {
            stage_cp(ringU, cW + f * 4096, 1024, tid);
            CPC(); CPW0();
            __syncthreads();
            ULL acc[8];
#pragma unroll
            for (int i = 0; i < 8; i++) acc[i] = 0ull;
#pragma unroll 4
            for (int kk = 0; kk < 64; kk++) {
                ULL w = *(const ULL*)(ringF + kk * 64 + 2 * tn);
#pragma unroll
                for (int i = 0; i < 8; i++) fma2(acc[i], dup2(zef[(m0 + i) * 68 + kk]), w);
            }
            __syncthreads();
#pragma unroll
            for (int i = 0; i < 8; i++) {
                float2 v = unpk(acc[i]);
                zef[(m0 + i) * 68 + 2 * tn] = v.x;
                zef[(m0 + i) * 68 + 2 * tn + 1] = v.y;
            }
            __syncthreads();
        }
        // pack masked z -> G3A ktiles 0..1 (bf16)
        for (int i = tid; i < 1024; i += 256) {
            int m = i >> 4, p = i & 15;
            int kt = p >> 3;
            int ln = (m & 7) * 4 + (p & 3);
            int rr = ((m >> 3) & 1) + 2 * ((p >> 2) & 1);
            g3aU[((m >> 4) * 6 + kt) * 128 + ln * 4 + rr] =
                pack_bf16(zef[m * 68 + 2 * p], zef[m * 68 + 2 * p + 1]);
        }
        // (sync happens at gemm entry)

        float acc[32][4];
        // G3: h = gelu([z*mask,ext] @ W0 + b0), K'=96
#pragma unroll
        for (int i = 0; i < 32; i++)
#pragma unroll
            for (int q = 0; q < 4; q++) acc[i][q] = 0.f;
        gemmW<6, 8, 4096, 6>(acc, g_W0p + f * 6 * 4096, g3aU, ringU, ringFU, tid, lane, wid);
        __syncthreads();
        epiH512(acc, sb, hAU, lane, wid);
        __syncthreads();

        // G4: h = gelu(h @ W1 + b1), K=512
#pragma unroll
        for (int i = 0; i < 32; i++)
#pragma unroll
            for (int q = 0; q < 4; q++) acc[i][q] = 0.f;
        gemmW<32, 8, 4096, 32>(acc, g_W1p + f * 32 * 4096, hAU, ringU, ringFU, tid, lane, wid);
        __syncthreads();
        epiH512(acc, sb + 512, hAU, lane, wid);
        __syncthreads();

        // G5: coupling (W2 cols 64..127), K=512, warp=1 ntile, 4 mtiles
#pragma unroll
        for (int i = 0; i < 4; i++)
#pragma unroll
            for (int q = 0; q < 4; q++) acc[i][q] = 0.f;
        gemmW<32, 1, 512, 32>(acc, g_W2p + f * 32 * 512, hAU, ringU, ringFU, tid, lane, wid);
        __syncthreads();
        {
            int cc = lane & 3, r = lane >> 2;
            int d = 32 + wid * 4 + cc;
            float sf = expf(scf[f * 64 + d]);
            float den = fmaxf(sf, 1.0f);
            float bs = sb[1088 + wid * 8 + 2 * cc];
            float bt = sb[1089 + wid * 8 + 2 * cc];
#pragma unroll
            for (int mtl = 0; mtl < 4; mtl++)
#pragma unroll
                for (int qh = 0; qh < 2; qh++) {
                    int m = mtl * 16 + r + 8 * qh;
                    float sr = acc[mtl][2 * qh] + bs;
                    float tr = acc[mtl][2 * qh + 1] + bt;
                    float s = tanhf(sr / den) * sf;
                    zef[m * 68 + d] = (zef[m * 68 + d] + tr) * expf(s);
                    ldj_acc += s;
                }
            __syncthreads();
        }
    }  // flows

    // output
    for (int i = tid; i < 4096; i += 256)
        outz[(long long)t0 * 64 + i] = zef[(i >> 6) * 68 + (i & 63)];
#pragma unroll
    for (int o = 16; o; o >>= 1) ldj_acc += __shfl_xor_sync(0xffffffffu, ldj_acc, o);
    if (lane == 0) wsum[wid] = ldj_acc;
    __syncthreads();
    if (tid == 0) {
        float s = 0.f;
#pragma unroll
        for (int i = 0; i < 8; i++) s += wsum[i];
        atomicAdd(&ldj[blockIdx.x >> 5], s);  // 32 blocks per batch
    }
}

// ---------------------------------------------------------------------------
extern "C" void kernel_launch(void* const* d_in, const int* in_sizes, int n_in,
                              void* d_out, int out_size) {
    const float* z = (const float*)d_in[0];
    const int* categ = (const int*)d_in[1];
    const float* embed = (const float*)d_in[2];
    const float* actnorm_W = (const float*)d_in[3];
    const float* actnorm_b = (const float*)d_in[4];
    const float* conv_W = (const float*)d_in[5];
    const float* scaling_factor = (const float*)d_in[6];
    const float* W0 = (const float*)d_in[7];
    const float* b0 = (const float*)d_in[8];
    const float* W1 = (const float*)d_in[9];
    const float* b1 = (const float*)d_in[10];
    const float* W2 = (const float*)d_in[11];
    const float* b2 = (const float*)d_in[12];

    float* outz = (float*)d_out;
    float* ldj = outz + (long long)TOKENS * 64;
    U32 *w0p, *w1p, *w2p;
    cudaGetSymbolAddress((void**)&w0p, g_W0p);
    cudaGetSymbolAddress((void**)&w1p, g_W1p);
    cudaGetSymbolAddress((void**)&w2p, g_W2p);

    cudaFuncSetAttribute(flow_kernel, cudaFuncAttributeMaxDynamicSharedMemorySize,
                         SMEMB);

    packB<<<dim3(6, 4), 256>>>(W0, w0p, 512, 6, 64, 0, 1);
    packB<<<dim3(32, 4), 256>>>(W1, w1p, 512, 32, 64, 0, 0);
    packB<<<dim3(32, 4), 256>>>(W2, w2p, 128, 32, 8, 64, 0);
    logdet_kernel<<<4, 64>>>(conv_W);
    init_ldj_kernel<<<1, 64>>>(ldj);
    flow_kernel<<<NBLK, 256, SMEMB>>>(z, categ, embed, actnorm_W, actnorm_b, conv_W,
                                      scaling_factor, b0, b1, b2, outz, ldj);
}

// round 9
// speedup vs baseline: 2.8060x; 1.0682x over previous
#include <cuda_runtime.h>
#include <cstdint>

// B=64,S=2048,D=64,E=64,H=512,F=4,V=32000
#define TOKENS (64 * 2048)
#define NBLK (TOKENS / 64)
typedef unsigned long long ULL;
typedef unsigned int U32;

__device__ float g_logdet[4];
__device__ U32 g_W0p[4 * 6 * 64 * 64];    // [f][kt][nt*64+lane*2+rr] bf16x2, K'=96
__device__ U32 g_W1p[4 * 32 * 64 * 64];   // K=512
__device__ U32 g_W2p[4 * 32 * 8 * 64];    // W2 cols 64..127, K=512

// smem float offsets
#define ZE 0        // 64x68 fp32 z
#define EXT 4352    // 64x64 fp32 ext
#define G3A 8448    // 3072 u32: A-frags bf16 [mtB][kt<6][128]
#define SB 11520    // b0[512] b1[512] b2[128] ab[128]
#define RING 12800  // 3 x 8192 u32 (32KB) staging ring
#define HA 37376    // 16384 u32: h A-frags bf16 [mt][kt<32][128]
#define SMEMF 53760
#define SMEMB (SMEMF * 4)  // 215040

// ---------------- helpers ----------------
__device__ __forceinline__ ULL dup2(float a) {
    ULL r; U32 ai = __float_as_uint(a);
    asm("mov.b64 %0, {%1, %1};" : "=l"(r) : "r"(ai));
    return r;
}
__device__ __forceinline__ void fma2(ULL& d, ULL a, ULL b) {
    asm("fma.rn.f32x2 %0, %1, %2, %0;" : "+l"(d) : "l"(a), "l"(b));
}
__device__ __forceinline__ float2 unpk(ULL v) {
    U32 lo, hi;
    asm("mov.b64 {%0, %1}, %2;" : "=r"(lo), "=r"(hi) : "l"(v));
    float2 r; r.x = __uint_as_float(lo); r.y = __uint_as_float(hi);
    return r;
}
__device__ __forceinline__ float gelu(float x) {
    return 0.5f * x * (1.0f + erff(x * 0.70710678118654752440f));
}
__device__ __forceinline__ U32 pack_bf16(float lo, float hi) {
    U32 r;
    asm("cvt.rn.bf16x2.f32 %0, %1, %2;" : "=r"(r) : "f"(hi), "f"(lo));
    return r;
}
__device__ __forceinline__ U32 smem_u32(const void* p) {
    U32 a;
    asm("{ .reg .u64 t; cvta.to.shared.u64 t, %1; cvt.u32.u64 %0, t; }" : "=r"(a) : "l"(p));
    return a;
}
#define CPA16(d, s) asm volatile("cp.async.cg.shared.global [%0], [%1], 16;" ::"r"(d), "l"(s))
#define CPC() asm volatile("cp.async.commit_group;" ::: "memory")
#define CPW0() asm volatile("cp.async.wait_group 0;" ::: "memory")
#define CPW1() asm volatile("cp.async.wait_group 1;" ::: "memory")

__device__ __forceinline__ void mma16(float* c, uint4 a, uint2 b) {
    asm volatile(
        "mma.sync.aligned.m16n8k16.row.col.f32.bf16.bf16.f32 "
        "{%0,%1,%2,%3},{%4,%5,%6,%7},{%8,%9},{%0,%1,%2,%3};"
        : "+f"(c[0]), "+f"(c[1]), "+f"(c[2]), "+f"(c[3])
        : "r"(a.x), "r"(a.y), "r"(a.z), "r"(a.w), "r"(b.x), "r"(b.y));
}
__device__ __forceinline__ void stage_cp(U32 dstU, const float* src, int n4, int tid) {
    for (int i = tid; i < n4; i += 256) CPA16(dstU + i * 16, src + i * 4);
}

// ---------------- weight pack: bf16 B-fragment order ----------------
__global__ void packB(const float* __restrict__ src, U32* __restrict__ dst, int N,
                      int KT, int NT, int nOff, int kMode) {
    int f = blockIdx.y, kt = blockIdx.x, tid = threadIdx.x;
    const float* s = src + (long long)f * (kMode ? 128 : 512) * N;
    U32* d = dst + (long long)(f * KT + kt) * NT * 64;
    for (int i = tid; i < NT * 64; i += 256) {
        int nt = i >> 6, j = i & 63, lane = j >> 1, rr = j & 1;
        int k0 = kt * 16 + 2 * (lane & 3) + 8 * rr;
        int n = nt * 8 + (lane >> 2) + nOff;
        if (kMode && k0 >= 32) k0 += 32;  // W0: skip masked-z rows 32..63
        d[i] = pack_bf16(s[k0 * N + n], s[(k0 + 1) * N + n]);
    }
}

// ---------------- slogdet (64x64 LU) ----------------
__global__ void logdet_kernel(const float* __restrict__ cW) {
    __shared__ float A[64][65];
    __shared__ int piv;
    int f = blockIdx.x, tid = threadIdx.x;
    for (int j = 0; j < 64; j++) A[j][tid] = cW[f * 4096 + j * 64 + tid];
    __syncthreads();
    for (int j = 0; j < 64; j++) {
        if (tid == 0) {
            int p = j; float mv = fabsf(A[j][j]);
            for (int i = j + 1; i < 64; i++) {
                float v = fabsf(A[i][j]);
                if (v > mv) { mv = v; p = i; }
            }
            piv = p;
        }
        __syncthreads();
        int p = piv;
        if (p != j) { float t = A[j][tid]; A[j][tid] = A[p][tid]; A[p][tid] = t; }
        __syncthreads();
        if (tid > j) {
            float fct = A[tid][j] / A[j][j];
            for (int k = j; k < 64; k++) A[tid][k] -= fct * A[j][k];
        }
        __syncthreads();
    }
    if (tid == 0) {
        float s = 0.f;
        for (int j = 0; j < 64; j++) s += logf(fabsf(A[j][j]));
        g_logdet[f] = s;
    }
}
__global__ void init_ldj_kernel(float* __restrict__ ldj) {
    if (threadIdx.x < 64) {
        float s = g_logdet[0] + g_logdet[1] + g_logdet[2] + g_logdet[3];
        ldj[threadIdx.x] = 2048.0f * s;
    }
}

// ---------------- gemm: warp = n-slice (NTW ntiles), all 4 m-tiles ----------
// TWO ktiles per iteration (32KB stage), 3-buffer ring, one barrier per iter.
template <int ITERS, int NTW, int HALF, int KTA>
__device__ __forceinline__ void gemmW(float (*acc)[4], const U32* __restrict__ Bg,
                                      const U32* __restrict__ AU, U32 ringU,
                                      const U32* __restrict__ ringFU, int tid,
                                      int lane, int wid) {
    __syncthreads();  // ring safe to overwrite
    for (int t = 0; t < 2 && t < ITERS; t++) {
        stage_cp(ringU + t * 32768, (const float*)(Bg + t * 2 * HALF), HALF / 2, tid);
        CPC();
    }
    for (int it = 0; it < ITERS; it++) {
        if (it + 1 < ITERS) { CPW1(); } else { CPW0(); }
        __syncthreads();
        if (it + 2 < ITERS) {
            stage_cp(ringU + ((it + 2) % 3) * 32768,
                     (const float*)(Bg + (it + 2) * 2 * HALF), HALF / 2, tid);
            CPC();
        }
        const U32* bp = ringFU + (it % 3) * 8192 + wid * (NTW * 64) + lane * 2;
#pragma unroll
        for (int h = 0; h < 2; h++) {
            int kt = 2 * it + h;
            const U32* bph = bp + h * HALF;
#pragma unroll
            for (int mtl = 0; mtl < 4; mtl++) {
                uint4 av = *(const uint4*)(AU + (mtl * KTA + kt) * 128 + lane * 4);
#pragma unroll
                for (int nt = 0; nt < NTW; nt++) {
                    uint2 bv = *(const uint2*)(bph + nt * 64);
                    mma16(acc[mtl * NTW + nt], av, bv);
                }
            }
        }
    }
}

// epilogue: gelu(acc+bias) -> hA bf16 A-frags
__device__ __forceinline__ void epiH512(float (*acc)[4], const float* __restrict__ bias,
                                        U32* __restrict__ hAU, int lane, int wid) {
    int c2 = 2 * (lane & 3);
#pragma unroll
    for (int mtl = 0; mtl < 4; mtl++)
#pragma unroll
        for (int nt = 0; nt < 8; nt++) {
            int ntg = wid * 8 + nt;
            float* a = acc[mtl * 8 + nt];
            int n0 = ntg * 8 + c2;
            float b0v = bias[n0], b1v = bias[n0 + 1];
            U32 base = (U32)(mtl * 32 + (ntg >> 1)) * 128 + lane * 4 + 2 * (ntg & 1);
            hAU[base + 0] = pack_bf16(gelu(a[0] + b0v), gelu(a[1] + b1v));
            hAU[base + 1] = pack_bf16(gelu(a[2] + b0v), gelu(a[3] + b1v));
        }
}

// ---------------- fused flow kernel: 64 tokens/CTA, 256 threads ----------------
__global__ __launch_bounds__(256, 1) void flow_kernel(
    const float* __restrict__ zin, const int* __restrict__ categ,
    const float* __restrict__ embed, const float* __restrict__ aW,
    const float* __restrict__ ab, const float* __restrict__ cW,
    const float* __restrict__ scf, const float* __restrict__ b0g,
    const float* __restrict__ b1g, const float* __restrict__ b2g,
    float* __restrict__ outz, float* __restrict__ ldj) {
    extern __shared__ float sm[];
    __shared__ int cat[64];
    __shared__ float wsum[8];
    const int tid = threadIdx.x, wid = tid >> 5, lane = tid & 31;
    const int m0 = wid * 8, tn = lane;
    const int t0 = blockIdx.x * 64;
    float* zef = sm + ZE;
    float* extf = sm + EXT;
    float* sb = sm + SB;
    float* ringF = sm + RING;
    U32* g3aU = (U32*)(sm + G3A);
    U32* hAU = (U32*)(sm + HA);
    const U32* ringFU = (const U32*)(sm + RING);
    const U32 ringU = smem_u32(sm) + RING * 4;

    // init loads
    for (int i = tid; i < 4096; i += 256)
        zef[(i >> 6) * 68 + (i & 63)] = zin[(long long)t0 * 64 + i];
    if (tid < 64) cat[tid] = categ[t0 + tid];
    __syncthreads();
    for (int i = tid; i < 1024; i += 256) {
        int m = i >> 4, e4 = i & 15;
        *(float4*)(extf + i * 4) = ((const float4*)embed)[(long long)cat[m] * 16 + e4];
    }
    __syncthreads();
    // pack ext -> G3A ktiles 2..5 (bf16 A-frags), once
    for (int i = tid; i < 2048; i += 256) {
        int m = i >> 5, p = i & 31;
        int kt = 2 + (p >> 3);
        int ln = (m & 7) * 4 + (p & 3);
        int rr = ((m >> 3) & 1) + 2 * ((p >> 2) & 1);
        g3aU[((m >> 4) * 6 + kt) * 128 + ln * 4 + rr] =
            pack_bf16(extf[m * 64 + 2 * p], extf[m * 64 + 2 * p + 1]);
    }
    float ldj_acc = 0.f;

#pragma unroll 1
    for (int f = 0; f < 4; f++) {
        __syncthreads();
        for (int i = tid; i < 512; i += 256) sb[i] = b0g[f * 512 + i];
        for (int i = tid; i < 512; i += 256) sb[512 + i] = b1g[f * 512 + i];
        if (tid < 128) sb[1024 + tid] = b2g[f * 128 + tid];
        if (tid < 128) sb[1152 + tid] = ab[f * 128 + tid];
        stage_cp(ringU, aW + f * 8192, 2048, tid);
        CPC(); CPW0();
        __syncthreads();

        // G1: actnorm (scalar fp32x2, ext fp32)
        {
            ULL acc[8][2];
#pragma unroll
            for (int i = 0; i < 8; i++) acc[i][0] = acc[i][1] = 0ull;
#pragma unroll 4
            for (int kk = 0; kk < 64; kk++) {
                ULL w0 = *(const ULL*)(ringF + kk * 128 + 2 * tn);
                ULL w1 = *(const ULL*)(ringF + kk * 128 + 64 + 2 * tn);
#pragma unroll
                for (int i = 0; i < 8; i++) {
                    ULL a = dup2(extf[(m0 + i) * 64 + kk]);
                    fma2(acc[i][0], a, w0);
                    fma2(acc[i][1], a, w1);
                }
            }
            int d0 = 2 * tn;
            float ab0 = sb[1152 + d0], ab1 = sb[1153 + d0];
            float as0 = sb[1216 + d0], as1 = sb[1217 + d0];
#pragma unroll
            for (int i = 0; i < 8; i++) {
                float2 bi = unpk(acc[i][0]);
                float2 sc = unpk(acc[i][1]);
                float s0 = tanhf(sc.x + as0), s1 = tanhf(sc.y + as1);
                float* zp = zef + (m0 + i) * 68 + d0;
                zp[0] = (zp[0] + bi.x + ab0) * expf(s0);
                zp[1] = (zp[1] + bi.y + ab1) * expf(s1);
                ldj_acc += s0 + s1;
            }
            __syncthreads();
        }
        // G2: 1x1 conv (scalar fp32x2)
        {
            stage_cp(ringU, cW + f * 4096, 1024, tid);
            CPC(); CPW0();
            __syncthreads();
            ULL acc[8];
#pragma unroll
            for (int i = 0; i < 8; i++) acc[i] = 0ull;
#pragma unroll 4
            for (int kk = 0; kk < 64; kk++) {
                ULL w = *(const ULL*)(ringF + kk * 64 + 2 * tn);
#pragma unroll
                for (int i = 0; i < 8; i++) fma2(acc[i], dup2(zef[(m0 + i) * 68 + kk]), w);
            }
            __syncthreads();
#pragma unroll
            for (int i = 0; i < 8; i++) {
                float2 v = unpk(acc[i]);
                zef[(m0 + i) * 68 + 2 * tn] = v.x;
                zef[(m0 + i) * 68 + 2 * tn + 1] = v.y;
            }
            __syncthreads();
        }
        // pack masked z -> G3A ktiles 0..1 (bf16)
        for (int i = tid; i < 1024; i += 256) {
            int m = i >> 4, p = i & 15;
            int kt = p >> 3;
            int ln = (m & 7) * 4 + (p & 3);
            int rr = ((m >> 3) & 1) + 2 * ((p >> 2) & 1);
            g3aU[((m >> 4) * 6 + kt) * 128 + ln * 4 + rr] =
                pack_bf16(zef[m * 68 + 2 * p], zef[m * 68 + 2 * p + 1]);
        }
        // (sync happens at gemm entry)

        float acc[32][4];
        // G3: h = gelu([z*mask,ext] @ W0 + b0), K'=96 (3 double-iters)
#pragma unroll
        for (int i = 0; i < 32; i++)
#pragma unroll
            for (int q = 0; q < 4; q++) acc[i][q] = 0.f;
        gemmW<3, 8, 4096, 6>(acc, g_W0p + f * 6 * 4096, g3aU, ringU, ringFU, tid, lane, wid);
        __syncthreads();
        epiH512(acc, sb, hAU, lane, wid);
        __syncthreads();

        // G4: h = gelu(h @ W1 + b1), K=512 (16 double-iters)
#pragma unroll
        for (int i = 0; i < 32; i++)
#pragma unroll
            for (int q = 0; q < 4; q++) acc[i][q] = 0.f;
        gemmW<16, 8, 4096, 32>(acc, g_W1p + f * 32 * 4096, hAU, ringU, ringFU, tid, lane, wid);
        __syncthreads();
        epiH512(acc, sb + 512, hAU, lane, wid);
        __syncthreads();

        // G5: coupling (W2 cols 64..127), K=512, warp=1 ntile (16 double-iters)
#pragma unroll
        for (int i = 0; i < 4; i++)
#pragma unroll
            for (int q = 0; q < 4; q++) acc[i][q] = 0.f;
        gemmW<16, 1, 512, 32>(acc, g_W2p + f * 32 * 512, hAU, ringU, ringFU, tid, lane, wid);
        __syncthreads();
        {
            int cc = lane & 3, r = lane >> 2;
            int d = 32 + wid * 4 + cc;
            float sf = expf(scf[f * 64 + d]);
            float den = fmaxf(sf, 1.0f);
            float bs = sb[1088 + wid * 8 + 2 * cc];
            float bt = sb[1089 + wid * 8 + 2 * cc];
#pragma unroll
            for (int mtl = 0; mtl < 4; mtl++)
#pragma unroll
                for (int qh = 0; qh < 2; qh++) {
                    int m = mtl * 16 + r + 8 * qh;
                    float sr = acc[mtl][2 * qh] + bs;
                    float tr = acc[mtl][2 * qh + 1] + bt;
                    float s = tanhf(sr / den) * sf;
                    zef[m * 68 + d] = (zef[m * 68 + d] + tr) * expf(s);
                    ldj_acc += s;
                }
            __syncthreads();
        }
    }  // flows

    // output
    for (int i = tid; i < 4096; i += 256)
        outz[(long long)t0 * 64 + i] = zef[(i >> 6) * 68 + (i & 63)];
#pragma unroll
    for (int o = 16; o; o >>= 1) ldj_acc += __shfl_xor_sync(0xffffffffu, ldj_acc, o);
    if (lane == 0) wsum[wid] = ldj_acc;
    __syncthreads();
    if (tid == 0) {
        float s = 0.f;
#pragma unroll
        for (int i = 0; i < 8; i++) s += wsum[i];
        atomicAdd(&ldj[blockIdx.x >> 5], s);  // 32 blocks per batch
    }
}

// ---------------------------------------------------------------------------
extern "C" void kernel_launch(void* const* d_in, const int* in_sizes, int n_in,
                              void* d_out, int out_size) {
    const float* z = (const float*)d_in[0];
    const int* categ = (const int*)d_in[1];
    const float* embed = (const float*)d_in[2];
    const float* actnorm_W = (const float*)d_in[3];
    const float* actnorm_b = (const float*)d_in[4];
    const float* conv_W = (const float*)d_in[5];
    const float* scaling_factor = (const float*)d_in[6];
    const float* W0 = (const float*)d_in[7];
    const float* b0 = (const float*)d_in[8];
    const float* W1 = (const float*)d_in[9];
    const float* b1 = (const float*)d_in[10];
    const float* W2 = (const float*)d_in[11];
    const float* b2 = (const float*)d_in[12];

    float* outz = (float*)d_out;
    float* ldj = outz + (long long)TOKENS * 64;
    U32 *w0p, *w1p, *w2p;
    cudaGetSymbolAddress((void**)&w0p, g_W0p);
    cudaGetSymbolAddress((void**)&w1p, g_W1p);
    cudaGetSymbolAddress((void**)&w2p, g_W2p);

    cudaFuncSetAttribute(flow_kernel, cudaFuncAttributeMaxDynamicSharedMemorySize,
                         SMEMB);

    packB<<<dim3(6, 4), 256>>>(W0, w0p, 512, 6, 64, 0, 1);
    packB<<<dim3(32, 4), 256>>>(W1, w1p, 512, 32, 64, 0, 0);
    packB<<<dim3(32, 4), 256>>>(W2, w2p, 128, 32, 8, 64, 0);
    logdet_kernel<<<4, 64>>>(conv_W);
    init_ldj_kernel<<<1, 64>>>(ldj);
    flow_kernel<<<NBLK, 256, SMEMB>>>(z, categ, embed, actnorm_W, actnorm_b, conv_W,
                                      scaling_factor, b0, b1, b2, outz, ldj);
}

// round 11
// speedup vs baseline: 3.7345x; 1.3309x over previous
#include <cuda_runtime.h>
#include <cstdint>

// B=64,S=2048,D=64,E=64,H=512,F=4,V=32000
#define TOKENS (64 * 2048)
#define MT 32
#define NBLK (TOKENS / MT)  // 4096
typedef unsigned long long ULL;
typedef unsigned int U32;

__device__ float g_logdet[4];
__device__ U32 g_W0p[4 * 6 * 4096];   // [f][kt<6][nt(64)*64] bf16x2 frags (K'=96)
__device__ U32 g_W1p[4 * 32 * 4096];  // [f][kt<32][...]
__device__ U32 g_W2p[4 * 8 * 2048];   // [f][tile<8][s(4)][nt(8)][64], cols 64..127

// smem float offsets (total 27520 floats = 110080 B -> 2 CTAs/SM)
#define ZE 0       // 32 x 68 fp32 z
#define EXT 2176   // 32 x 64 fp32 ext (persistent)
#define SB 4224    // b0[512] b1[512] b2[128] ab[128]
#define G3A 5504   // 1536 u32: A frags [mtl(2)][kt(6)][128]
#define HA 7040    // 8192 u32: h A frags [mtl(2)][kt(32)][128]
#define RING 15232 // 3 x 4096 u32 (16KB slots)
#define SMEMF 27520
#define SMEMB (SMEMF * 4)

// ---------------- helpers ----------------
__device__ __forceinline__ ULL dup2(float a) {
    ULL r; U32 ai = __float_as_uint(a);
    asm("mov.b64 %0, {%1, %1};" : "=l"(r) : "r"(ai));
    return r;
}
__device__ __forceinline__ void fma2(ULL& d, ULL a, ULL b) {
    asm("fma.rn.f32x2 %0, %1, %2, %0;" : "+l"(d) : "l"(a), "l"(b));
}
__device__ __forceinline__ float2 unpk(ULL v) {
    U32 lo, hi;
    asm("mov.b64 {%0, %1}, %2;" : "=r"(lo), "=r"(hi) : "l"(v));
    float2 r; r.x = __uint_as_float(lo); r.y = __uint_as_float(hi);
    return r;
}
__device__ __forceinline__ float gelu(float x) {
    return 0.5f * x * (1.0f + erff(x * 0.70710678118654752440f));
}
__device__ __forceinline__ U32 pack_bf16(float lo, float hi) {
    U32 r;
    asm("cvt.rn.bf16x2.f32 %0, %1, %2;" : "=r"(r) : "f"(hi), "f"(lo));
    return r;
}
__device__ __forceinline__ U32 smem_u32(const void* p) {
    U32 a;
    asm("{ .reg .u64 t; cvta.to.shared.u64 t, %1; cvt.u32.u64 %0, t; }" : "=r"(a) : "l"(p));
    return a;
}
#define CPA16(d, s) asm volatile("cp.async.cg.shared.global [%0], [%1], 16;" ::"r"(d), "l"(s))
#define CPC() asm volatile("cp.async.commit_group;" ::: "memory")
#define CPW0() asm volatile("cp.async.wait_group 0;" ::: "memory")
#define CPW1() asm volatile("cp.async.wait_group 1;" ::: "memory")

__device__ __forceinline__ void mma16(float* c, uint4 a, uint2 b) {
    asm volatile(
        "mma.sync.aligned.m16n8k16.row.col.f32.bf16.bf16.f32 "
        "{%0,%1,%2,%3},{%4,%5,%6,%7},{%8,%9},{%0,%1,%2,%3};"
        : "+f"(c[0]), "+f"(c[1]), "+f"(c[2]), "+f"(c[3])
        : "r"(a.x), "r"(a.y), "r"(a.z), "r"(a.w), "r"(b.x), "r"(b.y));
}
__device__ __forceinline__ void stage_cp(U32 dstU, const float* src, int n4, int tid) {
    for (int i = tid; i < n4; i += 256) CPA16(dstU + i * 16, src + i * 4);
}

// ---------------- weight packs (bf16 B-fragment order) ----------------
__global__ void packB(const float* __restrict__ src, U32* __restrict__ dst, int N,
                      int KT, int NT, int nOff, int kMode) {
    int f = blockIdx.y, kt = blockIdx.x, tid = threadIdx.x;
    const float* s = src + (long long)f * (kMode ? 128 : 512) * N;
    U32* d = dst + (long long)(f * KT + kt) * NT * 64;
    for (int i = tid; i < NT * 64; i += 256) {
        int nt = i >> 6, j = i & 63, lane = j >> 1, rr = j & 1;
        int k0 = kt * 16 + 2 * (lane & 3) + 8 * rr;
        int n = nt * 8 + (lane >> 2) + nOff;
        if (kMode && k0 >= 32) k0 += 32;  // W0: skip masked-z rows 32..63
        d[i] = pack_bf16(s[k0 * N + n], s[(k0 + 1) * N + n]);
    }
}
// W2 cols 64..127: [f][tile(8)][s(4)][nt(8)][64]
__global__ void packW2(const float* __restrict__ W2, U32* __restrict__ dst) {
    int f = blockIdx.y, t = blockIdx.x, tid = threadIdx.x;
    const float* s = W2 + (long long)f * 512 * 128;
    U32* d = dst + (f * 8 + t) * 2048;
    for (int i = tid; i < 2048; i += 256) {
        int ss = i >> 9, j = i & 511;
        int nt = j >> 6, jj = j & 63, lane = jj >> 1, rr = jj & 1;
        int k0 = (t * 4 + ss) * 16 + 2 * (lane & 3) + 8 * rr;
        int n = 64 + nt * 8 + (lane >> 2);
        d[i] = pack_bf16(s[k0 * 128 + n], s[(k0 + 1) * 128 + n]);
    }
}

// ---------------- slogdet (64x64 LU) ----------------
__global__ void logdet_kernel(const float* __restrict__ cW) {
    __shared__ float A[64][65];
    __shared__ int piv;
    int f = blockIdx.x, tid = threadIdx.x;
    for (int j = 0; j < 64; j++) A[j][tid] = cW[f * 4096 + j * 64 + tid];
    __syncthreads();
    for (int j = 0; j < 64; j++) {
        if (tid == 0) {
            int p = j; float mv = fabsf(A[j][j]);
            for (int i = j + 1; i < 64; i++) {
                float v = fabsf(A[i][j]);
                if (v > mv) { mv = v; p = i; }
            }
            piv = p;
        }
        __syncthreads();
        int p = piv;
        if (p != j) { float t = A[j][tid]; A[j][tid] = A[p][tid]; A[p][tid] = t; }
        __syncthreads();
        if (tid > j) {
            float fct = A[tid][j] / A[j][j];
            for (int k = j; k < 64; k++) A[tid][k] -= fct * A[j][k];
        }
        __syncthreads();
    }
    if (tid == 0) {
        float s = 0.f;
        for (int j = 0; j < 64; j++) s += logf(fabsf(A[j][j]));
        g_logdet[f] = s;
    }
}
__global__ void init_ldj_kernel(float* __restrict__ ldj) {
    if (threadIdx.x < 64) {
        float s = g_logdet[0] + g_logdet[1] + g_logdet[2] + g_logdet[3];
        ldj[threadIdx.x] = 2048.0f * s;
    }
}

// ------- gemm driver A: 16KB tiles, one k16 step, warp = 8 ntiles of N=512 ---
template <int ITERS, int KTA>
__device__ __forceinline__ void gemmN8(float (*acc)[4], const U32* __restrict__ Bg,
                                       const U32* __restrict__ AU, U32 ringU,
                                       const U32* __restrict__ ringFU, int tid,
                                       int lane, int wid) {
    __syncthreads();
    for (int t = 0; t < 2 && t < ITERS; t++) {
        stage_cp(ringU + t * 16384, (const float*)(Bg + t * 4096), 1024, tid);
        CPC();
    }
    for (int it = 0; it < ITERS; it++) {
        if (it + 1 < ITERS) { CPW1(); } else { CPW0(); }
        __syncthreads();
        if (it + 2 < ITERS) {
            stage_cp(ringU + ((it + 2) % 3) * 16384,
                     (const float*)(Bg + (U32)(it + 2) * 4096), 1024, tid);
            CPC();
        }
        const U32* bp = ringFU + (it % 3) * 4096 + wid * 512 + lane * 2;
        uint4 a0 = *(const uint4*)(AU + (0 * KTA + it) * 128 + lane * 4);
        uint4 a1 = *(const uint4*)(AU + (1 * KTA + it) * 128 + lane * 4);
#pragma unroll
        for (int nt = 0; nt < 8; nt++) {
            uint2 bv = *(const uint2*)(bp + nt * 64);
            mma16(acc[nt], a0, bv);
            mma16(acc[8 + nt], a1, bv);
        }
    }
}
// ------- gemm driver B (G5): 8KB tiles, 4 k16 steps, warp = 1 ntile of N=64 --
__device__ __forceinline__ void gemmG5(float (*acc)[4], const U32* __restrict__ Bg,
                                       const U32* __restrict__ AU, U32 ringU,
                                       const U32* __restrict__ ringFU, int tid,
                                       int lane, int wid) {
    __syncthreads();
    for (int t = 0; t < 2; t++) {
        stage_cp(ringU + t * 16384, (const float*)(Bg + t * 2048), 512, tid);
        CPC();
    }
    for (int it = 0; it < 8; it++) {
        if (it + 1 < 8) { CPW1(); } else { CPW0(); }
        __syncthreads();
        if (it + 2 < 8) {
            stage_cp(ringU + ((it + 2) % 3) * 16384,
                     (const float*)(Bg + (U32)(it + 2) * 2048), 512, tid);
            CPC();
        }
        const U32* slot = ringFU + (it % 3) * 4096 + wid * 64 + lane * 2;
#pragma unroll
        for (int s = 0; s < 4; s++) {
            int kt = it * 4 + s;
            uint2 bv = *(const uint2*)(slot + s * 512);
            uint4 a0 = *(const uint4*)(AU + (0 * 32 + kt) * 128 + lane * 4);
            uint4 a1 = *(const uint4*)(AU + (1 * 32 + kt) * 128 + lane * 4);
            mma16(acc[0], a0, bv);
            mma16(acc[1], a1, bv);
        }
    }
}

// epilogue: gelu(acc+bias) -> hA bf16 A-frags (mtl 0..1, nt 0..7 per warp)
__device__ __forceinline__ void epiH(float (*acc)[4], const float* __restrict__ bias,
                                     U32* __restrict__ hAU, int lane, int wid) {
    int c2 = 2 * (lane & 3);
#pragma unroll
    for (int mtl = 0; mtl < 2; mtl++)
#pragma unroll
        for (int nt = 0; nt < 8; nt++) {
            int ntg = wid * 8 + nt;
            float* a = acc[mtl * 8 + nt];
            int n0 = ntg * 8 + c2;
            float b0v = bias[n0], b1v = bias[n0 + 1];
            U32 base = (U32)(mtl * 32 + (ntg >> 1)) * 128 + lane * 4 + 2 * (ntg & 1);
            hAU[base + 0] = pack_bf16(gelu(a[0] + b0v), gelu(a[1] + b1v));
            hAU[base + 1] = pack_bf16(gelu(a[2] + b0v), gelu(a[3] + b1v));
        }
}

// ---------------- fused flow kernel: 32 tokens/CTA, 256 thr, 2 CTA/SM -------
__global__ __launch_bounds__(256, 2) void flow_kernel(
    const float* __restrict__ zin, const int* __restrict__ categ,
    const float* __restrict__ embed, const float* __restrict__ aW,
    const float* __restrict__ ab, const float* __restrict__ cW,
    const float* __restrict__ scf, const float* __restrict__ b0g,
    const float* __restrict__ b1g, const float* __restrict__ b2g,
    float* __restrict__ outz, float* __restrict__ ldj) {
    extern __shared__ float sm[];
    __shared__ int cat[32];
    __shared__ float wsum[8];
    const int tid = threadIdx.x, wid = tid >> 5, lane = tid & 31;
    const int m0 = wid * 4, tn = lane;
    const int t0 = blockIdx.x * MT;
    float* zef = sm + ZE;
    float* extf = sm + EXT;
    float* sb = sm + SB;
    float* ringF = sm + RING;
    U32* g3aU = (U32*)(sm + G3A);
    U32* hAU = (U32*)(sm + HA);
    const U32* ringFU = (const U32*)(sm + RING);
    const U32 ringU = smem_u32(sm) + RING * 4;

    for (int i = tid; i < 2048; i += 256)
        zef[(i >> 6) * 68 + (i & 63)] = zin[(long long)t0 * 64 + i];
    if (tid < 32) cat[tid] = categ[t0 + tid];
    __syncthreads();
    for (int i = tid; i < 512; i += 256) {
        int m = i >> 4, e4 = i & 15;
        *(float4*)(extf + i * 4) = ((const float4*)embed)[(long long)cat[m] * 16 + e4];
    }
    __syncthreads();
    // pack ext -> G3A kt 2..5 (bf16 A-frags), once
    for (int i = tid; i < 1024; i += 256) {
        int m = i >> 5, pe = i & 31;           // pair over 64 ext cols
        int kt = 2 + (pe >> 3), p = pe & 7;
        int ln = (m & 7) * 4 + (p & 3);
        int rr = ((m >> 3) & 1) + 2 * ((p >> 2) & 1);
        g3aU[((m >> 4) * 6 + kt) * 128 + ln * 4 + rr] =
            pack_bf16(extf[m * 64 + 2 * pe], extf[m * 64 + 2 * pe + 1]);
    }
    float ldj_acc = 0.f;

#pragma unroll 1
    for (int f = 0; f < 4; f++) {
        __syncthreads();
        for (int i = tid; i < 512; i += 256) sb[i] = b0g[f * 512 + i];
        for (int i = tid; i < 512; i += 256) sb[512 + i] = b1g[f * 512 + i];
        if (tid < 128) sb[1024 + tid] = b2g[f * 128 + tid];
        if (tid < 128) sb[1152 + tid] = ab[f * 128 + tid];
        stage_cp(ringU, aW + f * 8192, 2048, tid);  // 32KB fp32 into ring
        CPC(); CPW0();
        __syncthreads();

        // G1: actnorm (scalar fp32x2) — 4 tokens per warp
        {
            ULL acc[4][2];
#pragma unroll
            for (int i = 0; i < 4; i++) acc[i][0] = acc[i][1] = 0ull;
#pragma unroll 4
            for (int kk = 0; kk < 64; kk++) {
                ULL w0 = *(const ULL*)(ringF + kk * 128 + 2 * tn);
                ULL w1 = *(const ULL*)(ringF + kk * 128 + 64 + 2 * tn);
#pragma unroll
                for (int i = 0; i < 4; i++) {
                    ULL a = dup2(extf[(m0 + i) * 64 + kk]);
                    fma2(acc[i][0], a, w0);
                    fma2(acc[i][1], a, w1);
                }
            }
            int d0 = 2 * tn;
            float ab0 = sb[1152 + d0], ab1 = sb[1153 + d0];
            float as0 = sb[1216 + d0], as1 = sb[1217 + d0];
#pragma unroll
            for (int i = 0; i < 4; i++) {
                float2 bi = unpk(acc[i][0]);
                float2 sc = unpk(acc[i][1]);
                float s0 = tanhf(sc.x + as0), s1 = tanhf(sc.y + as1);
                float* zp = zef + (m0 + i) * 68 + d0;
                zp[0] = (zp[0] + bi.x + ab0) * expf(s0);
                zp[1] = (zp[1] + bi.y + ab1) * expf(s1);
                ldj_acc += s0 + s1;
            }
            __syncthreads();
        }
        // G2: 1x1 conv (scalar fp32x2)
        {
            stage_cp(ringU, cW + f * 4096, 1024, tid);
            CPC(); CPW0();
            __syncthreads();
            ULL acc[4];
#pragma unroll
            for (int i = 0; i < 4; i++) acc[i] = 0ull;
#pragma unroll 4
            for (int kk = 0; kk < 64; kk++) {
                ULL w = *(const ULL*)(ringF + kk * 64 + 2 * tn);
#pragma unroll
                for (int i = 0; i < 4; i++) fma2(acc[i], dup2(zef[(m0 + i) * 68 + kk]), w);
            }
            __syncthreads();
#pragma unroll
            for (int i = 0; i < 4; i++) {
                float2 v = unpk(acc[i]);
                zef[(m0 + i) * 68 + 2 * tn] = v.x;
                zef[(m0 + i) * 68 + 2 * tn + 1] = v.y;
            }
            __syncthreads();
        }
        // pack masked z -> G3A kt 0..1
        for (int i = tid; i < 512; i += 256) {
            int m = i >> 4, pe = i & 15;
            int kt = pe >> 3, p = pe & 7;
            int ln = (m & 7) * 4 + (p & 3);
            int rr = ((m >> 3) & 1) + 2 * ((p >> 2) & 1);
            g3aU[((m >> 4) * 6 + kt) * 128 + ln * 4 + rr] =
                pack_bf16(zef[m * 68 + 2 * pe], zef[m * 68 + 2 * pe + 1]);
        }

        float acc[16][4];
        // G3: K'=96 (6 iters)
#pragma unroll
        for (int i = 0; i < 16; i++)
#pragma unroll
            for (int q = 0; q < 4; q++) acc[i][q] = 0.f;
        gemmN8<6, 6>(acc, g_W0p + f * 6 * 4096, g3aU, ringU, ringFU, tid, lane, wid);
        __syncthreads();
        epiH(acc, sb, hAU, lane, wid);
        __syncthreads();

        // G4: K=512 (32 iters)
#pragma unroll
        for (int i = 0; i < 16; i++)
#pragma unroll
            for (int q = 0; q < 4; q++) acc[i][q] = 0.f;
        gemmN8<32, 32>(acc, g_W1p + f * 32 * 4096, hAU, ringU, ringFU, tid, lane, wid);
        __syncthreads();
        epiH(acc, sb + 512, hAU, lane, wid);
        __syncthreads();

        // G5: N=64, K=512 (8 iters)
#pragma unroll
        for (int i = 0; i < 2; i++)
#pragma unroll
            for (int q = 0; q < 4; q++) acc[i][q] = 0.f;
        gemmG5(acc, g_W2p + f * 8 * 2048, hAU, ringU, ringFU, tid, lane, wid);
        __syncthreads();
        {
            int cc = lane & 3, r = lane >> 2;
            int d = 32 + wid * 4 + cc;
            float sf = expf(scf[f * 64 + d]);
            float den = fmaxf(sf, 1.0f);
            float bs = sb[1088 + wid * 8 + 2 * cc];
            float bt = sb[1089 + wid * 8 + 2 * cc];
#pragma unroll
            for (int mtl = 0; mtl < 2; mtl++)
#pragma unroll
                for (int qh = 0; qh < 2; qh++) {
                    int m = mtl * 16 + r + 8 * qh;
                    float sr = acc[mtl][2 * qh] + bs;
                    float tr = acc[mtl][2 * qh + 1] + bt;
                    float s = tanhf(sr / den) * sf;
                    zef[m * 68 + d] = (zef[m * 68 + d] + tr) * expf(s);
                    ldj_acc += s;
                }
            __syncthreads();
        }
    }  // flows

    for (int i = tid; i < 2048; i += 256)
        outz[(long long)t0 * 64 + i] = zef[(i >> 6) * 68 + (i & 63)];
#pragma unroll
    for (int o = 16; o; o >>= 1) ldj_acc += __shfl_xor_sync(0xffffffffu, ldj_acc, o);
    if (lane == 0) wsum[wid] = ldj_acc;
    __syncthreads();
    if (tid == 0) {
        float s = 0.f;
#pragma unroll
        for (int i = 0; i < 8; i++) s += wsum[i];
        atomicAdd(&ldj[blockIdx.x >> 6], s);  // 64 blocks per batch
    }
}

// ---------------------------------------------------------------------------
extern "C" void kernel_launch(void* const* d_in, const int* in_sizes, int n_in,
                              void* d_out, int out_size) {
    const float* z = (const float*)d_in[0];
    const int* categ = (const int*)d_in[1];
    const float* embed = (const float*)d_in[2];
    const float* actnorm_W = (const float*)d_in[3];
    const float* actnorm_b = (const float*)d_in[4];
    const float* conv_W = (const float*)d_in[5];
    const float* scaling_factor = (const float*)d_in[6];
    const float* W0 = (const float*)d_in[7];
    const float* b0 = (const float*)d_in[8];
    const float* W1 = (const float*)d_in[9];
    const float* b1 = (const float*)d_in[10];
    const float* W2 = (const float*)d_in[11];
    const float* b2 = (const float*)d_in[12];

    float* outz = (float*)d_out;
    float* ldj = outz + (long long)TOKENS * 64;
    U32 *w0p, *w1p, *w2p;
    cudaGetSymbolAddress((void**)&w0p, g_W0p);
    cudaGetSymbolAddress((void**)&w1p, g_W1p);
    cudaGetSymbolAddress((void**)&w2p, g_W2p);

    cudaFuncSetAttribute(flow_kernel, cudaFuncAttributeMaxDynamicSharedMemorySize, SMEMB);

    packB<<<dim3(6, 4), 256>>>(W0, w0p, 512, 6, 64, 0, 1);
    packB<<<dim3(32, 4), 256>>>(W1, w1p, 512, 32, 64, 0, 0);
    packW2<<<dim3(8, 4), 256>>>(W2, w2p);
    logdet_kernel<<<4, 64>>>(conv_W);
    init_ldj_kernel<<<1, 64>>>(ldj);
    flow_kernel<<<NBLK, 256, SMEMB>>>(z, categ, embed, actnorm_W, actnorm_b, conv_W,
                                      scaling_factor, b0, b1, b2, outz, ldj);
}

// round 12
// speedup vs baseline: 3.8002x; 1.0176x over previous
#include <cuda_runtime.h>
#include <cuda_fp16.h>
#include <cstdint>

// B=64,S=2048,D=64,E=64,H=512,F=4,V=32000
#define TOKENS (64 * 2048)
#define MT 32
#define NBLK (TOKENS / MT)  // 4096
typedef unsigned long long ULL;
typedef unsigned int U32;

__device__ float g_logdet[4];
__device__ U32 g_W0p[4 * 6 * 4096];   // [f][kt<6][nt(64)*64] f16x2 frags (K'=96)
__device__ U32 g_W1p[4 * 32 * 4096];  // [f][kt<32][...]
__device__ U32 g_W2p[4 * 8 * 2048];   // [f][tile<8][s(4)][nt(8)][64], cols 64..127

// smem float offsets (total 27520 floats = 110080 B -> 2 CTAs/SM)
#define ZE 0       // 32 x 68 fp32 z
#define EXT 2176   // 32 x 64 fp32 ext (persistent)
#define SB 4224    // b0[512] b1[512] b2[128] ab[128]
#define G3A 5504   // 1536 u32: A frags [mtl(2)][kt(6)][128]
#define HA 7040    // 8192 u32: h A frags [mtl(2)][kt(32)][128]
#define RING 15232 // 3 x 4096 u32 (16KB slots)
#define SMEMF 27520
#define SMEMB (SMEMF * 4)

// ---------------- helpers ----------------
__device__ __forceinline__ ULL dup2(float a) {
    ULL r; U32 ai = __float_as_uint(a);
    asm("mov.b64 %0, {%1, %1};" : "=l"(r) : "r"(ai));
    return r;
}
__device__ __forceinline__ void fma2(ULL& d, ULL a, ULL b) {
    asm("fma.rn.f32x2 %0, %1, %2, %0;" : "+l"(d) : "l"(a), "l"(b));
}
__device__ __forceinline__ float2 unpk(ULL v) {
    U32 lo, hi;
    asm("mov.b64 {%0, %1}, %2;" : "=r"(lo), "=r"(hi) : "l"(v));
    float2 r; r.x = __uint_as_float(lo); r.y = __uint_as_float(hi);
    return r;
}
__device__ __forceinline__ float gelu(float x) {
    return 0.5f * x * (1.0f + erff(x * 0.70710678118654752440f));
}
// pack two fp32 -> f16x2 (lo in low half)
__device__ __forceinline__ U32 pack_h(float lo, float hi) {
    U32 r;
    asm("cvt.rn.f16x2.f32 %0, %1, %2;" : "=r"(r) : "f"(hi), "f"(lo));
    return r;
}
__device__ __forceinline__ float2 unpk_h(U32 v) {
    __half2 h = *reinterpret_cast<__half2*>(&v);
    return __half22float2(h);
}
__device__ __forceinline__ U32 smem_u32(const void* p) {
    U32 a;
    asm("{ .reg .u64 t; cvta.to.shared.u64 t, %1; cvt.u32.u64 %0, t; }" : "=r"(a) : "l"(p));
    return a;
}
#define CPA16(d, s) asm volatile("cp.async.cg.shared.global [%0], [%1], 16;" ::"r"(d), "l"(s))
#define CPC() asm volatile("cp.async.commit_group;" ::: "memory")
#define CPW0() asm volatile("cp.async.wait_group 0;" ::: "memory")
#define CPW1() asm volatile("cp.async.wait_group 1;" ::: "memory")

// f16 x f16 -> f16 accumulate (2 c-regs of f16x2)
__device__ __forceinline__ void mma16h(U32* c, uint4 a, uint2 b) {
    asm volatile(
        "mma.sync.aligned.m16n8k16.row.col.f16.f16.f16.f16 "
        "{%0,%1},{%2,%3,%4,%5},{%6,%7},{%0,%1};"
        : "+r"(c[0]), "+r"(c[1])
        : "r"(a.x), "r"(a.y), "r"(a.z), "r"(a.w), "r"(b.x), "r"(b.y));
}
__device__ __forceinline__ void stage_cp(U32 dstU, const float* src, int n4, int tid) {
    for (int i = tid; i < n4; i += 256) CPA16(dstU + i * 16, src + i * 4);
}

// ---------------- weight packs (f16 B-fragment order) ----------------
__global__ void packB(const float* __restrict__ src, U32* __restrict__ dst, int N,
                      int KT, int NT, int nOff, int kMode) {
    int f = blockIdx.y, kt = blockIdx.x, tid = threadIdx.x;
    const float* s = src + (long long)f * (kMode ? 128 : 512) * N;
    U32* d = dst + (long long)(f * KT + kt) * NT * 64;
    for (int i = tid; i < NT * 64; i += 256) {
        int nt = i >> 6, j = i & 63, lane = j >> 1, rr = j & 1;
        int k0 = kt * 16 + 2 * (lane & 3) + 8 * rr;
        int n = nt * 8 + (lane >> 2) + nOff;
        if (kMode && k0 >= 32) k0 += 32;  // W0: skip masked-z rows 32..63
        d[i] = pack_h(s[k0 * N + n], s[(k0 + 1) * N + n]);
    }
}
// W2 cols 64..127: [f][tile(8)][s(4)][nt(8)][64]
__global__ void packW2(const float* __restrict__ W2, U32* __restrict__ dst) {
    int f = blockIdx.y, t = blockIdx.x, tid = threadIdx.x;
    const float* s = W2 + (long long)f * 512 * 128;
    U32* d = dst + (f * 8 + t) * 2048;
    for (int i = tid; i < 2048; i += 256) {
        int ss = i >> 9, j = i & 511;
        int nt = j >> 6, jj = j & 63, lane = jj >> 1, rr = jj & 1;
        int k0 = (t * 4 + ss) * 16 + 2 * (lane & 3) + 8 * rr;
        int n = 64 + nt * 8 + (lane >> 2);
        d[i] = pack_h(s[k0 * 128 + n], s[(k0 + 1) * 128 + n]);
    }
}

// ---------------- slogdet (64x64 LU) ----------------
__global__ void logdet_kernel(const float* __restrict__ cW) {
    __shared__ float A[64][65];
    __shared__ int piv;
    int f = blockIdx.x, tid = threadIdx.x;
    for (int j = 0; j < 64; j++) A[j][tid] = cW[f * 4096 + j * 64 + tid];
    __syncthreads();
    for (int j = 0; j < 64; j++) {
        if (tid == 0) {
            int p = j; float mv = fabsf(A[j][j]);
            for (int i = j + 1; i < 64; i++) {
                float v = fabsf(A[i][j]);
                if (v > mv) { mv = v; p = i; }
            }
            piv = p;
        }
        __syncthreads();
        int p = piv;
        if (p != j) { float t = A[j][tid]; A[j][tid] = A[p][tid]; A[p][tid] = t; }
        __syncthreads();
        if (tid > j) {
            float fct = A[tid][j] / A[j][j];
            for (int k = j; k < 64; k++) A[tid][k] -= fct * A[j][k];
        }
        __syncthreads();
    }
    if (tid == 0) {
        float s = 0.f;
        for (int j = 0; j < 64; j++) s += logf(fabsf(A[j][j]));
        g_logdet[f] = s;
    }
}
__global__ void init_ldj_kernel(float* __restrict__ ldj) {
    if (threadIdx.x < 64) {
        float s = g_logdet[0] + g_logdet[1] + g_logdet[2] + g_logdet[3];
        ldj[threadIdx.x] = 2048.0f * s;
    }
}

// ------- gemm driver A: 16KB tiles, one k16 step, warp = 8 ntiles of N=512 ---
template <int ITERS, int KTA>
__device__ __forceinline__ void gemmN8(U32 (*acc)[2], const U32* __restrict__ Bg,
                                       const U32* __restrict__ AU, U32 ringU,
                                       const U32* __restrict__ ringFU, int tid,
                                       int lane, int wid) {
    __syncthreads();
    for (int t = 0; t < 2 && t < ITERS; t++) {
        stage_cp(ringU + t * 16384, (const float*)(Bg + t * 4096), 1024, tid);
        CPC();
    }
    for (int it = 0; it < ITERS; it++) {
        if (it + 1 < ITERS) { CPW1(); } else { CPW0(); }
        __syncthreads();
        if (it + 2 < ITERS) {
            stage_cp(ringU + ((it + 2) % 3) * 16384,
                     (const float*)(Bg + (U32)(it + 2) * 4096), 1024, tid);
            CPC();
        }
        const U32* bp = ringFU + (it % 3) * 4096 + wid * 512 + lane * 2;
        uint4 a0 = *(const uint4*)(AU + (0 * KTA + it) * 128 + lane * 4);
        uint4 a1 = *(const uint4*)(AU + (1 * KTA + it) * 128 + lane * 4);
#pragma unroll
        for (int nt = 0; nt < 8; nt++) {
            uint2 bv = *(const uint2*)(bp + nt * 64);
            mma16h(acc[nt], a0, bv);
            mma16h(acc[8 + nt], a1, bv);
        }
    }
}
// ------- gemm driver B (G5): 8KB tiles, 4 k16 steps, warp = 1 ntile of N=64 --
__device__ __forceinline__ void gemmG5(U32 (*acc)[2], const U32* __restrict__ Bg,
                                       const U32* __restrict__ AU, U32 ringU,
                                       const U32* __restrict__ ringFU, int tid,
                                       int lane, int wid) {
    __syncthreads();
    for (int t = 0; t < 2; t++) {
        stage_cp(ringU + t * 16384, (const float*)(Bg + t * 2048), 512, tid);
        CPC();
    }
    for (int it = 0; it < 8; it++) {
        if (it + 1 < 8) { CPW1(); } else { CPW0(); }
        __syncthreads();
        if (it + 2 < 8) {
            stage_cp(ringU + ((it + 2) % 3) * 16384,
                     (const float*)(Bg + (U32)(it + 2) * 2048), 512, tid);
            CPC();
        }
        const U32* slot = ringFU + (it % 3) * 4096 + wid * 64 + lane * 2;
#pragma unroll
        for (int s = 0; s < 4; s++) {
            int kt = it * 4 + s;
            uint2 bv = *(const uint2*)(slot + s * 512);
            uint4 a0 = *(const uint4*)(AU + (0 * 32 + kt) * 128 + lane * 4);
            uint4 a1 = *(const uint4*)(AU + (1 * 32 + kt) * 128 + lane * 4);
            mma16h(acc[0], a0, bv);
            mma16h(acc[1], a1, bv);
        }
    }
}

// epilogue: gelu(acc+bias) -> hA f16 A-frags (mtl 0..1, nt 0..7 per warp)
__device__ __forceinline__ void epiH(U32 (*acc)[2], const float* __restrict__ bias,
                                     U32* __restrict__ hAU, int lane, int wid) {
    int c2 = 2 * (lane & 3);
#pragma unroll
    for (int mtl = 0; mtl < 2; mtl++)
#pragma unroll
        for (int nt = 0; nt < 8; nt++) {
            int ntg = wid * 8 + nt;
            float2 v0 = unpk_h(acc[mtl * 8 + nt][0]);  // row r,    cols c2,c2+1
            float2 v1 = unpk_h(acc[mtl * 8 + nt][1]);  // row r+8,  cols c2,c2+1
            int n0 = ntg * 8 + c2;
            float b0v = bias[n0], b1v = bias[n0 + 1];
            U32 base = (U32)(mtl * 32 + (ntg >> 1)) * 128 + lane * 4 + 2 * (ntg & 1);
            hAU[base + 0] = pack_h(gelu(v0.x + b0v), gelu(v0.y + b1v));
            hAU[base + 1] = pack_h(gelu(v1.x + b0v), gelu(v1.y + b1v));
        }
}

// ---------------- fused flow kernel: 32 tokens/CTA, 256 thr, 2 CTA/SM -------
__global__ __launch_bounds__(256, 2) void flow_kernel(
    const float* __restrict__ zin, const int* __restrict__ categ,
    const float* __restrict__ embed, const float* __restrict__ aW,
    const float* __restrict__ ab, const float* __restrict__ cW,
    const float* __restrict__ scf, const float* __restrict__ b0g,
    const float* __restrict__ b1g, const float* __restrict__ b2g,
    float* __restrict__ outz, float* __restrict__ ldj) {
    extern __shared__ float sm[];
    __shared__ int cat[32];
    __shared__ float wsum[8];
    const int tid = threadIdx.x, wid = tid >> 5, lane = tid & 31;
    const int m0 = wid * 4, tn = lane;
    const int t0 = blockIdx.x * MT;
    float* zef = sm + ZE;
    float* extf = sm + EXT;
    float* sb = sm + SB;
    float* ringF = sm + RING;
    U32* g3aU = (U32*)(sm + G3A);
    U32* hAU = (U32*)(sm + HA);
    const U32* ringFU = (const U32*)(sm + RING);
    const U32 ringU = smem_u32(sm) + RING * 4;

    for (int i = tid; i < 2048; i += 256)
        zef[(i >> 6) * 68 + (i & 63)] = zin[(long long)t0 * 64 + i];
    if (tid < 32) cat[tid] = categ[t0 + tid];
    __syncthreads();
    for (int i = tid; i < 512; i += 256) {
        int m = i >> 4, e4 = i & 15;
        *(float4*)(extf + i * 4) = ((const float4*)embed)[(long long)cat[m] * 16 + e4];
    }
    __syncthreads();
    // pack ext -> G3A kt 2..5 (f16 A-frags), once
    for (int i = tid; i < 1024; i += 256) {
        int m = i >> 5, pe = i & 31;  // pair over 64 ext cols
        int kt = 2 + (pe >> 3), p = pe & 7;
        int ln = (m & 7) * 4 + (p & 3);
        int rr = ((m >> 3) & 1) + 2 * ((p >> 2) & 1);
        g3aU[((m >> 4) * 6 + kt) * 128 + ln * 4 + rr] =
            pack_h(extf[m * 64 + 2 * pe], extf[m * 64 + 2 * pe + 1]);
    }
    float ldj_acc = 0.f;

#pragma unroll 1
    for (int f = 0; f < 4; f++) {
        __syncthreads();
        for (int i = tid; i < 512; i += 256) sb[i] = b0g[f * 512 + i];
        for (int i = tid; i < 512; i += 256) sb[512 + i] = b1g[f * 512 + i];
        if (tid < 128) sb[1024 + tid] = b2g[f * 128 + tid];
        if (tid < 128) sb[1152 + tid] = ab[f * 128 + tid];
        stage_cp(ringU, aW + f * 8192, 2048, tid);  // 32KB fp32 into ring
        CPC(); CPW0();
        __syncthreads();

        // G1: actnorm (scalar fp32x2) — 4 tokens per warp
        {
            ULL acc[4][2];
#pragma unroll
            for (int i = 0; i < 4; i++) acc[i][0] = acc[i][1] = 0ull;
#pragma unroll 4
            for (int kk = 0; kk < 64; kk++) {
                ULL w0 = *(const ULL*)(ringF + kk * 128 + 2 * tn);
                ULL w1 = *(const ULL*)(ringF + kk * 128 + 64 + 2 * tn);
#pragma unroll
                for (int i = 0; i < 4; i++) {
                    ULL a = dup2(extf[(m0 + i) * 64 + kk]);
                    fma2(acc[i][0], a, w0);
                    fma2(acc[i][1], a, w1);
                }
            }
            int d0 = 2 * tn;
            float ab0 = sb[1152 + d0], ab1 = sb[1153 + d0];
            float as0 = sb[1216 + d0], as1 = sb[1217 + d0];
#pragma unroll
            for (int i = 0; i < 4; i++) {
                float2 bi = unpk(acc[i][0]);
                float2 sc = unpk(acc[i][1]);
                float s0 = tanhf(sc.x + as0), s1 = tanhf(sc.y + as1);
                float* zp = zef + (m0 + i) * 68 + d0;
                zp[0] = (zp[0] + bi.x + ab0) * expf(s0);
                zp[1] = (zp[1] + bi.y + ab1) * expf(s1);
                ldj_acc += s0 + s1;
            }
            __syncthreads();
        }
        // G2: 1x1 conv (scalar fp32x2)
        {
            stage_cp(ringU, cW + f * 4096, 1024, tid);
            CPC(); CPW0();
            __syncthreads();
            ULL acc[4];
#pragma unroll
            for (int i = 0; i < 4; i++) acc[i] = 0ull;
#pragma unroll 4
            for (int kk = 0; kk < 64; kk++) {
                ULL w = *(const ULL*)(ringF + kk * 64 + 2 * tn);
#pragma unroll
                for (int i = 0; i < 4; i++) fma2(acc[i], dup2(zef[(m0 + i) * 68 + kk]), w);
            }
            __syncthreads();
#pragma unroll
            for (int i = 0; i < 4; i++) {
                float2 v = unpk(acc[i]);
                zef[(m0 + i) * 68 + 2 * tn] = v.x;
                zef[(m0 + i) * 68 + 2 * tn + 1] = v.y;
            }
            __syncthreads();
        }
        // pack masked z -> G3A kt 0..1
        for (int i = tid; i < 512; i += 256) {
            int m = i >> 4, pe = i & 15;
            int kt = pe >> 3, p = pe & 7;
            int ln = (m & 7) * 4 + (p & 3);
            int rr = ((m >> 3) & 1) + 2 * ((p >> 2) & 1);
            g3aU[((m >> 4) * 6 + kt) * 128 + ln * 4 + rr] =
                pack_h(zef[m * 68 + 2 * pe], zef[m * 68 + 2 * pe + 1]);
        }

        U32 acc[16][2];
        // G3: K'=96 (6 iters)
#pragma unroll
        for (int i = 0; i < 16; i++) { acc[i][0] = 0u; acc[i][1] = 0u; }
        gemmN8<6, 6>(acc, g_W0p + f * 6 * 4096, g3aU, ringU, ringFU, tid, lane, wid);
        __syncthreads();
        epiH(acc, sb, hAU, lane, wid);
        __syncthreads();

        // G4: K=512 (32 iters)
#pragma unroll
        for (int i = 0; i < 16; i++) { acc[i][0] = 0u; acc[i][1] = 0u; }
        gemmN8<32, 32>(acc, g_W1p + f * 32 * 4096, hAU, ringU, ringFU, tid, lane, wid);
        __syncthreads();
        epiH(acc, sb + 512, hAU, lane, wid);
        __syncthreads();

        // G5: N=64, K=512 (8 iters)
#pragma unroll
        for (int i = 0; i < 2; i++) { acc[i][0] = 0u; acc[i][1] = 0u; }
        gemmG5(acc, g_W2p + f * 8 * 2048, hAU, ringU, ringFU, tid, lane, wid);
        __syncthreads();
        {
            int cc = lane & 3, r = lane >> 2;
            int d = 32 + wid * 4 + cc;
            float sf = expf(scf[f * 64 + d]);
            float den = fmaxf(sf, 1.0f);
            float bs = sb[1088 + wid * 8 + 2 * cc];
            float bt = sb[1089 + wid * 8 + 2 * cc];
#pragma unroll
            for (int mtl = 0; mtl < 2; mtl++)
#pragma unroll
                for (int qh = 0; qh < 2; qh++) {
                    int m = mtl * 16 + r + 8 * qh;
                    float2 v = unpk_h(acc[mtl][qh]);  // (s, t) at cols c2, c2+1
                    float sr = v.x + bs;
                    float tr = v.y + bt;
                    float s = tanhf(sr / den) * sf;
                    zef[m * 68 + d] = (zef[m * 68 + d] + tr) * expf(s);
                    ldj_acc += s;
                }
            __syncthreads();
        }
    }  // flows

    for (int i = tid; i < 2048; i += 256)
        outz[(long long)t0 * 64 + i] = zef[(i >> 6) * 68 + (i & 63)];
#pragma unroll
    for (int o = 16; o; o >>= 1) ldj_acc += __shfl_xor_sync(0xffffffffu, ldj_acc, o);
    if (lane == 0) wsum[wid] = ldj_acc;
    __syncthreads();
    if (tid == 0) {
        float s = 0.f;
#pragma unroll
        for (int i = 0; i < 8; i++) s += wsum[i];
        atomicAdd(&ldj[blockIdx.x >> 6], s);  // 64 blocks per batch
    }
}

// ---------------------------------------------------------------------------
extern "C" void kernel_launch(void* const* d_in, const int* in_sizes, int n_in,
                              void* d_out, int out_size) {
    const float* z = (const float*)d_in[0];
    const int* categ = (const int*)d_in[1];
    const float* embed = (const float*)d_in[2];
    const float* actnorm_W = (const float*)d_in[3];
    const float* actnorm_b = (const float*)d_in[4];
    const float* conv_W = (const float*)d_in[5];
    const float* scaling_factor = (const float*)d_in[6];
    const float* W0 = (const float*)d_in[7];
    const float* b0 = (const float*)d_in[8];
    const float* W1 = (const float*)d_in[9];
    const float* b1 = (const float*)d_in[10];
    const float* W2 = (const float*)d_in[11];
    const float* b2 = (const float*)d_in[12];

    float* outz = (float*)d_out;
    float* ldj = outz + (long long)TOKENS * 64;
    U32 *w0p, *w1p, *w2p;
    cudaGetSymbolAddress((void**)&w0p, g_W0p);
    cudaGetSymbolAddress((void**)&w1p, g_W1p);
    cudaGetSymbolAddress((void**)&w2p, g_W2p);

    cudaFuncSetAttribute(flow_kernel, cudaFuncAttributeMaxDynamicSharedMemorySize, SMEMB);

    packB<<<dim3(6, 4), 256>>>(W0, w0p, 512, 6, 64, 0, 1);
    packB<<<dim3(32, 4), 256>>>(W1, w1p, 512, 32, 64, 0, 0);
    packW2<<<dim3(8, 4), 256>>>(W2, w2p);
    logdet_kernel<<<4, 64>>>(conv_W);
    init_ldj_kernel<<<1, 64>>>(ldj);
    flow_kernel<<<NBLK, 256, SMEMB>>>(z, categ, embed, actnorm_W, actnorm_b, conv_W,
                                      scaling_factor, b0, b1, b2, outz, ldj);
}